// round 15
// baseline (speedup 1.0000x reference)
#include <cuda_runtime.h>
#include <cuda_fp16.h>
#include <math.h>
#include <stdint.h>

// ---------------- scratch (static device globals; no allocations) ----------
__device__ float    g_x   [4096*512];
__device__ float    g_x2  [4096*512];
__device__ uint32_t g_lnh [4096*256];     // LN output, half2 words
__device__ uint32_t g_mlph[4096*1024];    // fc1 output, half2 words
__device__ uint32_t g_q   [64*1024*16];   // half2 words, [bh][n][16]
__device__ uint32_t g_k   [64*1024*16];
__device__ uint32_t g_v   [64*1024*16];
__device__ uint32_t g_oh  [4096*256];     // flash output, half2 words
__device__ float    g_fin [4096*1024];
__device__ float    g_img [4*64*128*128];
__device__ float    g_c1  [4*16*128*128];
// packed weights (k-paired half2 words, [K/2][N])
__device__ uint32_t g_qkvw[8*256*1536];
__device__ uint32_t g_projw[8*256*512];
__device__ uint32_t g_fc1w[8*256*2048];
__device__ uint32_t g_fc2w[8*1024*512];
__device__ uint32_t g_finw[256*1024];

// ---------------- helpers --------------------------------------------------
__device__ __forceinline__ uint32_t h2u(__half2 h) {
    return *reinterpret_cast<uint32_t*>(&h);
}

__device__ __forceinline__ void mma_f16(float* c, const uint32_t* a, const uint32_t* b) {
    asm volatile(
        "mma.sync.aligned.m16n8k16.row.col.f32.f16.f16.f32 "
        "{%0,%1,%2,%3}, {%4,%5,%6,%7}, {%8,%9}, {%0,%1,%2,%3};"
        : "+f"(c[0]), "+f"(c[1]), "+f"(c[2]), "+f"(c[3])
        : "r"(a[0]), "r"(a[1]), "r"(a[2]), "r"(a[3]), "r"(b[0]), "r"(b[1]));
}

__device__ __forceinline__ void ldsm_x4(uint32_t& r0, uint32_t& r1, uint32_t& r2,
                                        uint32_t& r3, uint32_t addr) {
    asm volatile("ldmatrix.sync.aligned.m8n8.x4.shared.b16 {%0,%1,%2,%3}, [%4];"
        : "=r"(r0), "=r"(r1), "=r"(r2), "=r"(r3) : "r"(addr));
}

// ---------------- merged weight pack ---------------------------------------
__global__ void pack_all_kernel(const float* __restrict__ qkv_w, const float* __restrict__ proj_w,
                                const float* __restrict__ fc1_w, const float* __restrict__ fc2_w,
                                const float* __restrict__ fin_w,
                                uint32_t* __restrict__ qkvp, uint32_t* __restrict__ projp,
                                uint32_t* __restrict__ fc1p, uint32_t* __restrict__ fc2p,
                                uint32_t* __restrict__ finp) {
    const int S0 = 8*256*1536, S1 = S0 + 8*256*512, S2 = S1 + 8*256*2048,
              S3 = S2 + 8*1024*512, S4 = S3 + 256*1024;
    int t = (blockIdx.x * blockDim.x + threadIdx.x) * 4;
    if (t >= S4) return;
    const float* src; uint32_t* dst; int N; int base;
    if (t < S0)      { src = qkv_w;  dst = qkvp;  N = 1536; base = t; }
    else if (t < S1) { src = proj_w; dst = projp; N = 512;  base = t - S0; }
    else if (t < S2) { src = fc1_w;  dst = fc1p;  N = 2048; base = t - S1; }
    else if (t < S3) { src = fc2_w;  dst = fc2p;  N = 512;  base = t - S2; }
    else             { src = fin_w;  dst = finp;  N = 1024; base = t - S3; }
    int p = base / N, n = base - p * N;
    float4 r0 = *(const float4*)&src[(size_t)(2 * p) * N + n];
    float4 r1 = *(const float4*)&src[(size_t)(2 * p + 1) * N + n];
    uint4 o;
    o.x = h2u(__floats2half2_rn(r0.x, r1.x));
    o.y = h2u(__floats2half2_rn(r0.y, r1.y));
    o.z = h2u(__floats2half2_rn(r0.z, r1.z));
    o.w = h2u(__floats2half2_rn(r0.w, r1.w));
    *(uint4*)&dst[base] = o;
}

// ---------------- pos-embed add + LN (layer 0), warp per row ---------------
__global__ void add_pe_ln_kernel(const float* __restrict__ x,
                                 const float* __restrict__ gam, const float* __restrict__ bet,
                                 float* __restrict__ outF, uint32_t* __restrict__ outH) {
    int row = (blockIdx.x * blockDim.x + threadIdx.x) >> 5;
    int lane = threadIdx.x & 31;
    if (row >= 4096) return;
    int p = row & 1023;
    int pi = p >> 5, pj = p & 31;
    const float4* xp = (const float4*)(x + (size_t)row * 512);
    float4 v[4];
    float s = 0.f;
#pragma unroll
    for (int i = 0; i < 4; i++) {
        v[i] = xp[lane + i * 32];
        int c0 = (lane + i * 32) * 4;
        float* vf = (float*)&v[i];
#pragma unroll
        for (int j = 0; j < 4; j++) {
            int c = c0 + j;
            int pos = (c < 256) ? pj : pi;
            int cc = c & 255;
            int m = cc & 127;
            float om = __expf(-(float)m * 0.0719558141f);
            float a = (float)pos * om;
            vf[j] += (cc < 128) ? sinf(a) : cosf(a);
        }
        s += v[i].x + v[i].y + v[i].z + v[i].w;
    }
#pragma unroll
    for (int o = 16; o > 0; o >>= 1) s += __shfl_xor_sync(0xffffffffu, s, o);
    float mu = s * (1.f / 512.f);
    float sq = 0.f;
#pragma unroll
    for (int i = 0; i < 4; i++) {
        float dx = v[i].x - mu, dy = v[i].y - mu, dz = v[i].z - mu, dw = v[i].w - mu;
        sq += dx * dx + dy * dy + dz * dz + dw * dw;
    }
#pragma unroll
    for (int o = 16; o > 0; o >>= 1) sq += __shfl_xor_sync(0xffffffffu, sq, o);
    float rstd = rsqrtf(sq * (1.f / 512.f) + 1e-5f);
    float4* fp = (float4*)(outF + (size_t)row * 512);
    uint32_t* op = outH + (size_t)row * 256;
#pragma unroll
    for (int i = 0; i < 4; i++) {
        fp[lane + i * 32] = v[i];
        float4 gg = ((const float4*)gam)[lane + i * 32];
        float4 bb = ((const float4*)bet)[lane + i * 32];
        float y0 = (v[i].x - mu) * rstd * gg.x + bb.x;
        float y1 = (v[i].y - mu) * rstd * gg.y + bb.y;
        float y2 = (v[i].z - mu) * rstd * gg.z + bb.z;
        float y3 = (v[i].w - mu) * rstd * gg.w + bb.w;
        uint2 wds;
        wds.x = h2u(__floats2half2_rn(y0, y1));
        wds.y = h2u(__floats2half2_rn(y2, y3));
        *(uint2*)&op[2 * (lane + i * 32)] = wds;
    }
}

// ---------------- GEMM (N=512, full-row tile) + bias + res + fused LN ------
// tile 32 rows x 512 cols, 256 thr, 8 warps (each warp 64 cols).
// outF = acc+bias+res (fp32); outH = LN(outF) (half2; gam null -> no affine).
__global__ void __launch_bounds__(256) sgemm_ln_kernel(
        const uint32_t* __restrict__ A, const uint32_t* __restrict__ B,
        const float* __restrict__ bias, const float* __restrict__ res,
        float* __restrict__ outF, uint32_t* __restrict__ outH,
        const float* __restrict__ gam, const float* __restrict__ bet,
        int K, float eps) {
    const int N = 512;
    __shared__ uint32_t As[32 * 20];
    __shared__ uint32_t Bs[16 * 520];
    __shared__ float redS[32][9];
    __shared__ float redQ[32][9];
    __shared__ float s_mu[32], s_rs[32];
    int tid = threadIdx.x;
    int w = tid >> 5, lane = tid & 31;
    int g = lane >> 2, tig = lane & 3;
    int bm = blockIdx.x * 32;
    int Kw = K >> 1;
    int NIT = K >> 5;

    int arow = tid >> 3, ac2 = (tid & 7) * 2;   // A: 512 words, uint2/thread
    uint32_t as_base = (uint32_t)__cvta_generic_to_shared(As);
    uint32_t a_addr = as_base + ((((lane & 15)) * 20 + (lane >> 4) * 4) << 2);

    float acc[2][8][4] = {};
    uint2 pa;
    uint4 pb[8];
    pa = *(const uint2*)&A[(size_t)(bm + arow) * Kw + ac2];
#pragma unroll
    for (int i = 0; i < 8; i++) {
        int idx = i * 256 + tid;
        int p = idx >> 7, c4 = idx & 127;
        pb[i] = *(const uint4*)&B[(size_t)p * N + c4 * 4];
    }

    for (int it = 0; it < NIT; it++) {
        *(uint2*)&As[arow * 20 + ac2] = pa;
#pragma unroll
        for (int i = 0; i < 8; i++) {
            int idx = i * 256 + tid;
            int p = idx >> 7, c4 = idx & 127;
            *(uint4*)&Bs[p * 520 + c4 * 4] = pb[i];
        }
        __syncthreads();
        if (it + 1 < NIT) {
            int kw0 = (it + 1) * 16;
            pa = *(const uint2*)&A[(size_t)(bm + arow) * Kw + kw0 + ac2];
#pragma unroll
            for (int i = 0; i < 8; i++) {
                int idx = i * 256 + tid;
                int p = idx >> 7, c4 = idx & 127;
                pb[i] = *(const uint4*)&B[(size_t)(kw0 + p) * N + c4 * 4];
            }
        }
#pragma unroll
        for (int ks = 0; ks < 2; ks++) {
            int kw = ks * 8;
            uint32_t a[2][4], b[8][2];
#pragma unroll
            for (int mt = 0; mt < 2; mt++)
                ldsm_x4(a[mt][0], a[mt][1], a[mt][2], a[mt][3],
                        a_addr + mt * 1280 + ks * 32);
#pragma unroll
            for (int nt = 0; nt < 8; nt++) {
                int nc = w * 64 + nt * 8;
                b[nt][0] = Bs[(kw + tig) * 520 + nc + g];
                b[nt][1] = Bs[(kw + 4 + tig) * 520 + nc + g];
            }
#pragma unroll
            for (int mt = 0; mt < 2; mt++)
#pragma unroll
                for (int nt = 0; nt < 8; nt++)
                    mma_f16(acc[mt][nt], a[mt], b[nt]);
        }
        __syncthreads();
    }

    // epilogue: bias + res, write outF, fused LN
#pragma unroll
    for (int mt = 0; mt < 2; mt++) {
#pragma unroll
        for (int nt = 0; nt < 8; nt++) {
            int col0 = w * 64 + nt * 8 + 2 * tig;
#pragma unroll
            for (int i = 0; i < 4; i++) {
                int lr = mt * 16 + g + (i >> 1) * 8;
                int col = col0 + (i & 1);
                float v = acc[mt][nt][i] + bias[col] + res[(size_t)(bm + lr) * N + col];
                acc[mt][nt][i] = v;
                outF[(size_t)(bm + lr) * N + col] = v;
            }
        }
    }
    // per-row partial sums (rows mt*16 + g + rh*8)
#pragma unroll
    for (int mt = 0; mt < 2; mt++) {
#pragma unroll
        for (int rh = 0; rh < 2; rh++) {
            float s = 0.f, q = 0.f;
#pragma unroll
            for (int nt = 0; nt < 8; nt++) {
                float v0 = acc[mt][nt][rh * 2], v1 = acc[mt][nt][rh * 2 + 1];
                s += v0 + v1;
                q += v0 * v0 + v1 * v1;
            }
            s += __shfl_xor_sync(0xffffffffu, s, 1);
            s += __shfl_xor_sync(0xffffffffu, s, 2);
            q += __shfl_xor_sync(0xffffffffu, q, 1);
            q += __shfl_xor_sync(0xffffffffu, q, 2);
            if (tig == 0) {
                int lr = mt * 16 + g + rh * 8;
                redS[lr][w] = s;
                redQ[lr][w] = q;
            }
        }
    }
    __syncthreads();
    if (tid < 32) {
        float s = 0.f, q = 0.f;
#pragma unroll
        for (int j = 0; j < 8; j++) { s += redS[tid][j]; q += redQ[tid][j]; }
        float mu = s * (1.f / 512.f);
        s_mu[tid] = mu;
        s_rs[tid] = rsqrtf(q * (1.f / 512.f) - mu * mu + eps);
    }
    __syncthreads();
#pragma unroll
    for (int mt = 0; mt < 2; mt++) {
#pragma unroll
        for (int rh = 0; rh < 2; rh++) {
            int lr = mt * 16 + g + rh * 8;
            float mu = s_mu[lr], rstd = s_rs[lr];
#pragma unroll
            for (int nt = 0; nt < 8; nt++) {
                int col0 = w * 64 + nt * 8 + 2 * tig;
                float y0 = (acc[mt][nt][rh * 2]     - mu) * rstd;
                float y1 = (acc[mt][nt][rh * 2 + 1] - mu) * rstd;
                if (gam) {
                    y0 = y0 * gam[col0] + bet[col0];
                    y1 = y1 * gam[col0 + 1] + bet[col0 + 1];
                }
                outH[(size_t)(bm + lr) * 256 + (col0 >> 1)] = h2u(__floats2half2_rn(y0, y1));
            }
        }
    }
}

// ---------------- fp16-operand GEMM, 128x128 tile (ldmatrix A) -------------
// mode 0: Cf=acc+bias; 2: Ch=half(GELU(acc+bias)).
__global__ void __launch_bounds__(256) sgemm_h16_kernel(
        const uint32_t* __restrict__ A, const uint32_t* __restrict__ B,
        const float* __restrict__ bias,
        float* __restrict__ Cf, uint32_t* __restrict__ Ch,
        int M, int N, int K, int mode) {
    __shared__ uint32_t As[128 * 20];
    __shared__ uint32_t Bs[16 * 136];
    int tid = threadIdx.x;
    int w = tid >> 5, lane = tid & 31;
    int g = lane >> 2, tig = lane & 3;
    int warp_m = w & 1, warp_n = w >> 1;
    int bm = blockIdx.y * 128, bn = blockIdx.x * 128;
    int Kw = K >> 1;

    int arow[2], ac4[2], bp[2], bn4[2];
#pragma unroll
    for (int i = 0; i < 2; i++) {
        int idx = i * 256 + tid;
        arow[i] = idx >> 2;  ac4[i] = idx & 3;
        bp[i]   = idx >> 5;  bn4[i] = idx & 31;
    }
    uint32_t as_base = (uint32_t)__cvta_generic_to_shared(As);
    uint32_t a_addr = as_base + (((warp_m * 64 + (lane & 15)) * 20 + (lane >> 4) * 4) << 2);

    float acc[4][4][4] = {};
    uint4 pa[2], pb[2];
#pragma unroll
    for (int i = 0; i < 2; i++) {
        pa[i] = *(const uint4*)&A[(size_t)(bm + arow[i]) * Kw + ac4[i] * 4];
        pb[i] = *(const uint4*)&B[(size_t)bp[i] * N + bn + bn4[i] * 4];
    }

    for (int k0 = 0; k0 < K; k0 += 32) {
#pragma unroll
        for (int i = 0; i < 2; i++) {
            *(uint4*)&As[arow[i] * 20 + ac4[i] * 4] = pa[i];
            *(uint4*)&Bs[bp[i] * 136 + bn4[i] * 4] = pb[i];
        }
        __syncthreads();
        if (k0 + 32 < K) {
            int kw0 = (k0 + 32) >> 1;
#pragma unroll
            for (int i = 0; i < 2; i++) {
                pa[i] = *(const uint4*)&A[(size_t)(bm + arow[i]) * Kw + kw0 + ac4[i] * 4];
                pb[i] = *(const uint4*)&B[(size_t)(kw0 + bp[i]) * N + bn + bn4[i] * 4];
            }
        }
#pragma unroll
        for (int ks = 0; ks < 2; ks++) {
            int kw = ks * 8;
            uint32_t a[4][4], b[4][2];
#pragma unroll
            for (int mt = 0; mt < 4; mt++)
                ldsm_x4(a[mt][0], a[mt][1], a[mt][2], a[mt][3],
                        a_addr + mt * 1280 + ks * 32);
#pragma unroll
            for (int nt = 0; nt < 4; nt++) {
                int nc = warp_n * 32 + nt * 8;
                b[nt][0] = Bs[(kw + tig) * 136 + nc + g];
                b[nt][1] = Bs[(kw + 4 + tig) * 136 + nc + g];
            }
#pragma unroll
            for (int mt = 0; mt < 4; mt++)
#pragma unroll
                for (int nt = 0; nt < 4; nt++)
                    mma_f16(acc[mt][nt], a[mt], b[nt]);
        }
        __syncthreads();
    }

#pragma unroll
    for (int mt = 0; mt < 4; mt++) {
#pragma unroll
        for (int nt = 0; nt < 4; nt++) {
            int row0 = bm + warp_m * 64 + mt * 16 + g;
            int col0 = bn + warp_n * 32 + nt * 8 + 2 * tig;
            if (mode == 2) {
#pragma unroll
                for (int rh = 0; rh < 2; rh++) {
                    int row = row0 + rh * 8;
                    float v0 = acc[mt][nt][rh * 2]     + bias[col0];
                    float v1 = acc[mt][nt][rh * 2 + 1] + bias[col0 + 1];
                    v0 = 0.5f * v0 * (1.f + erff(v0 * 0.70710678118654752f));
                    v1 = 0.5f * v1 * (1.f + erff(v1 * 0.70710678118654752f));
                    Ch[(size_t)row * (N >> 1) + (col0 >> 1)] = h2u(__floats2half2_rn(v0, v1));
                }
            } else {
#pragma unroll
                for (int i = 0; i < 4; i++) {
                    int row = row0 + (i >> 1) * 8;
                    int col = col0 + (i & 1);
                    Cf[(size_t)row * N + col] = acc[mt][nt][i] + bias[col];
                }
            }
        }
    }
}

// ---------------- QKV GEMM (fp16 operands, ldmatrix) + split + head-LN ----
__global__ void __launch_bounds__(256) sgemm_qkv_kernel(
        const uint32_t* __restrict__ A, const uint32_t* __restrict__ B,
        const float* __restrict__ bias,
        const float* __restrict__ nqg, const float* __restrict__ nqb,
        const float* __restrict__ nkg, const float* __restrict__ nkb,
        uint32_t* __restrict__ q, uint32_t* __restrict__ k,
        uint32_t* __restrict__ v) {
    const int N = 1536, K = 512, Kw = 256;
    __shared__ uint32_t As[128 * 20];
    __shared__ uint32_t Bs[16 * 136];
    int tid = threadIdx.x;
    int w = tid >> 5, lane = tid & 31;
    int g = lane >> 2, tig = lane & 3;
    int warp_m = w & 1, warp_n = w >> 1;
    int bm = blockIdx.y * 128, bn = blockIdx.x * 128;

    int arow[2], ac4[2], bp[2], bn4[2];
#pragma unroll
    for (int i = 0; i < 2; i++) {
        int idx = i * 256 + tid;
        arow[i] = idx >> 2;  ac4[i] = idx & 3;
        bp[i]   = idx >> 5;  bn4[i] = idx & 31;
    }
    uint32_t as_base = (uint32_t)__cvta_generic_to_shared(As);
    uint32_t a_addr = as_base + (((warp_m * 64 + (lane & 15)) * 20 + (lane >> 4) * 4) << 2);

    float acc[4][4][4] = {};
    uint4 pa[2], pb[2];
#pragma unroll
    for (int i = 0; i < 2; i++) {
        pa[i] = *(const uint4*)&A[(size_t)(bm + arow[i]) * Kw + ac4[i] * 4];
        pb[i] = *(const uint4*)&B[(size_t)bp[i] * N + bn + bn4[i] * 4];
    }

    for (int k0 = 0; k0 < K; k0 += 32) {
#pragma unroll
        for (int i = 0; i < 2; i++) {
            *(uint4*)&As[arow[i] * 20 + ac4[i] * 4] = pa[i];
            *(uint4*)&Bs[bp[i] * 136 + bn4[i] * 4] = pb[i];
        }
        __syncthreads();
        if (k0 + 32 < K) {
            int kw0 = (k0 + 32) >> 1;
#pragma unroll
            for (int i = 0; i < 2; i++) {
                pa[i] = *(const uint4*)&A[(size_t)(bm + arow[i]) * Kw + kw0 + ac4[i] * 4];
                pb[i] = *(const uint4*)&B[(size_t)(kw0 + bp[i]) * N + bn + bn4[i] * 4];
            }
        }
#pragma unroll
        for (int ks = 0; ks < 2; ks++) {
            int kw = ks * 8;
            uint32_t a[4][4], b[4][2];
#pragma unroll
            for (int mt = 0; mt < 4; mt++)
                ldsm_x4(a[mt][0], a[mt][1], a[mt][2], a[mt][3],
                        a_addr + mt * 1280 + ks * 32);
#pragma unroll
            for (int nt = 0; nt < 4; nt++) {
                int nc = warp_n * 32 + nt * 8;
                b[nt][0] = Bs[(kw + tig) * 136 + nc + g];
                b[nt][1] = Bs[(kw + 4 + tig) * 136 + nc + g];
            }
#pragma unroll
            for (int mt = 0; mt < 4; mt++)
#pragma unroll
                for (int nt = 0; nt < 4; nt++)
                    mma_f16(acc[mt][nt], a[mt], b[nt]);
        }
        __syncthreads();
    }

    int colbase = bn + warp_n * 32;
    int sec = colbase >> 9;
    int h = (colbase & 511) >> 5;
    const float sc = 0.17677669529663689f * 1.4426950408889634f;
    const float* gam = (sec == 0) ? nqg : nkg;
    const float* bet = (sec == 0) ? nqb : nkb;
    uint32_t* dst = (sec == 0) ? q : ((sec == 1) ? k : v);

#pragma unroll
    for (int mt = 0; mt < 4; mt++) {
#pragma unroll
        for (int rh = 0; rh < 2; rh++) {
            int row = bm + warp_m * 64 + mt * 16 + g + rh * 8;
            int bb = row >> 10, n = row & 1023;
            size_t offw = ((size_t)(bb * 16 + h) * 1024 + n) * 16;
            float vv[8];
#pragma unroll
            for (int nt = 0; nt < 4; nt++) {
#pragma unroll
                for (int j = 0; j < 2; j++) {
                    int col = colbase + nt * 8 + 2 * tig + j;
                    vv[nt * 2 + j] = acc[mt][nt][rh * 2 + j] + bias[col];
                }
            }
            if (sec == 2) {
#pragma unroll
                for (int nt = 0; nt < 4; nt++)
                    dst[offw + nt * 4 + tig] = h2u(__floats2half2_rn(vv[nt * 2], vv[nt * 2 + 1]));
            } else {
                float s = 0.f;
#pragma unroll
                for (int t = 0; t < 8; t++) s += vv[t];
                s += __shfl_xor_sync(0xffffffffu, s, 1);
                s += __shfl_xor_sync(0xffffffffu, s, 2);
                float mu = s * (1.f / 32.f);
                float sq = 0.f;
#pragma unroll
                for (int t = 0; t < 8; t++) { float d = vv[t] - mu; sq += d * d; }
                sq += __shfl_xor_sync(0xffffffffu, sq, 1);
                sq += __shfl_xor_sync(0xffffffffu, sq, 2);
                float rstd = rsqrtf(sq * (1.f / 32.f) + 1e-5f);
#pragma unroll
                for (int nt = 0; nt < 4; nt++) {
                    int d = nt * 8 + 2 * tig;
                    float y0 = (vv[nt * 2] - mu) * rstd * gam[d] + bet[d];
                    float y1 = (vv[nt * 2 + 1] - mu) * rstd * gam[d + 1] + bet[d + 1];
                    if (sec == 0) { y0 *= sc; y1 *= sc; }
                    dst[offw + nt * 4 + tig] = h2u(__floats2half2_rn(y0, y1));
                }
            }
        }
    }
}

// ---------------- flash attention (fp16, register P, ldmatrix K/V) --------
__global__ void __launch_bounds__(256, 3) flash_kernel(
        const uint32_t* __restrict__ q, const uint32_t* __restrict__ k,
        const uint32_t* __restrict__ v, uint32_t* __restrict__ o) {
    __shared__ uint32_t Qs[128 * 20];
    __shared__ uint32_t Ks[2][64 * 20];
    __shared__ uint32_t Vs[2][32 * 36];

    int bh = blockIdx.y;
    int bm = blockIdx.x * 128;
    int b = bh >> 4, h = bh & 15;
    int tid = threadIdx.x;
    int w = tid >> 5, lane = tid & 31;
    int g = lane >> 2, tig = lane & 3;

    const uint32_t* qb = q + ((size_t)bh * 1024 + bm) * 16;
    const uint32_t* kb = k + (size_t)bh * 1024 * 16;
    const uint32_t* vb = v + (size_t)bh * 1024 * 16;

#pragma unroll
    for (int i = 0; i < 2; i++) {
        int idx = i * 256 + tid;
        int r = idx >> 2, wv = idx & 3;
        *(uint4*)&Qs[r * 20 + wv * 4] = *(const uint4*)&qb[r * 16 + wv * 4];
    }
    {
        int r = tid >> 2, wv = tid & 3;
        *(uint4*)&Ks[0][r * 20 + wv * 4] = *(const uint4*)&kb[r * 16 + wv * 4];
#pragma unroll
        for (int i = 0; i < 2; i++) {
            int idx = i * 256 + tid;
            int p = idx >> 4, dp = idx & 15;
            uint32_t a = vb[(size_t)(2 * p) * 16 + dp];
            uint32_t bw = vb[(size_t)(2 * p + 1) * 16 + dp];
            Vs[0][(2 * dp) * 36 + p]     = __byte_perm(a, bw, 0x5410);
            Vs[0][(2 * dp + 1) * 36 + p] = __byte_perm(a, bw, 0x7632);
        }
    }
    __syncthreads();

    int frow = (lane & 7) + ((lane & 16) >> 1);
    int fcol = (lane & 8) >> 1;
    uint32_t qs_base = (uint32_t)__cvta_generic_to_shared(Qs);
    uint32_t ks_base0 = (uint32_t)__cvta_generic_to_shared(&Ks[0][0]);
    uint32_t vs_base0 = (uint32_t)__cvta_generic_to_shared(&Vs[0][0]);

    uint32_t qa[2][4];
    {
        uint32_t qaddr = qs_base + (((w * 16 + (lane & 15)) * 20 + (lane >> 4) * 4) << 2);
        ldsm_x4(qa[0][0], qa[0][1], qa[0][2], qa[0][3], qaddr);
        ldsm_x4(qa[1][0], qa[1][1], qa[1][2], qa[1][3], qaddr + 32);
    }

    float oacc[4][4] = {};
    float m0 = -1e30f, m1 = -1e30f, l0 = 0.f, l1 = 0.f;

    for (int j = 0; j < 16; j++) {
        int cur = j & 1;
        uint32_t ks_b = ks_base0 + cur * (64 * 20 * 4);
        uint32_t vs_b = vs_base0 + cur * (32 * 36 * 4);
        uint4 kreg;
        uint32_t va[2], vbw[2];
        if (j < 15) {
            int r = tid >> 2, wv = tid & 3;
            kreg = *(const uint4*)&kb[(size_t)((j + 1) * 64 + r) * 16 + wv * 4];
#pragma unroll
            for (int i = 0; i < 2; i++) {
                int idx = i * 256 + tid;
                int p = idx >> 4, dp = idx & 15;
                va[i]  = vb[(size_t)((j + 1) * 64 + 2 * p) * 16 + dp];
                vbw[i] = vb[(size_t)((j + 1) * 64 + 2 * p + 1) * 16 + dp];
            }
        }

        float s[8][4] = {};
#pragma unroll
        for (int ks = 0; ks < 2; ks++) {
            uint32_t bf[8][2];
#pragma unroll
            for (int tp = 0; tp < 4; tp++) {
                uint32_t addr = ks_b + (((tp * 16 + frow) * 20 + ks * 8 + fcol) << 2);
                ldsm_x4(bf[2 * tp][0], bf[2 * tp][1], bf[2 * tp + 1][0], bf[2 * tp + 1][1], addr);
            }
#pragma unroll
            for (int nt = 0; nt < 8; nt++)
                mma_f16(s[nt], qa[ks], bf[nt]);
        }

        float rm0 = -1e30f, rm1 = -1e30f;
#pragma unroll
        for (int nt = 0; nt < 8; nt++) {
            rm0 = fmaxf(rm0, fmaxf(s[nt][0], s[nt][1]));
            rm1 = fmaxf(rm1, fmaxf(s[nt][2], s[nt][3]));
        }
        rm0 = fmaxf(rm0, __shfl_xor_sync(0xffffffffu, rm0, 1));
        rm0 = fmaxf(rm0, __shfl_xor_sync(0xffffffffu, rm0, 2));
        rm1 = fmaxf(rm1, __shfl_xor_sync(0xffffffffu, rm1, 1));
        rm1 = fmaxf(rm1, __shfl_xor_sync(0xffffffffu, rm1, 2));
        float nm0 = fmaxf(m0, rm0), nm1 = fmaxf(m1, rm1);
        float al0 = exp2f(m0 - nm0), al1 = exp2f(m1 - nm1);
        float rs0 = 0.f, rs1 = 0.f;
#pragma unroll
        for (int nt = 0; nt < 8; nt++) {
            s[nt][0] = exp2f(s[nt][0] - nm0);
            s[nt][1] = exp2f(s[nt][1] - nm0);
            s[nt][2] = exp2f(s[nt][2] - nm1);
            s[nt][3] = exp2f(s[nt][3] - nm1);
            rs0 += s[nt][0] + s[nt][1];
            rs1 += s[nt][2] + s[nt][3];
        }
        rs0 += __shfl_xor_sync(0xffffffffu, rs0, 1);
        rs0 += __shfl_xor_sync(0xffffffffu, rs0, 2);
        rs1 += __shfl_xor_sync(0xffffffffu, rs1, 1);
        rs1 += __shfl_xor_sync(0xffffffffu, rs1, 2);
        l0 = l0 * al0 + rs0;
        l1 = l1 * al1 + rs1;
        m0 = nm0; m1 = nm1;
#pragma unroll
        for (int nt = 0; nt < 4; nt++) {
            oacc[nt][0] *= al0; oacc[nt][1] *= al0;
            oacc[nt][2] *= al1; oacc[nt][3] *= al1;
        }

#pragma unroll
        for (int ks2 = 0; ks2 < 4; ks2++) {
            uint32_t a[4];
            a[0] = h2u(__floats2half2_rn(s[2 * ks2][0],     s[2 * ks2][1]));
            a[1] = h2u(__floats2half2_rn(s[2 * ks2][2],     s[2 * ks2][3]));
            a[2] = h2u(__floats2half2_rn(s[2 * ks2 + 1][0], s[2 * ks2 + 1][1]));
            a[3] = h2u(__floats2half2_rn(s[2 * ks2 + 1][2], s[2 * ks2 + 1][3]));
            uint32_t bf[4][2];
#pragma unroll
            for (int tp = 0; tp < 2; tp++) {
                uint32_t addr = vs_b + (((tp * 16 + frow) * 36 + ks2 * 8 + fcol) << 2);
                ldsm_x4(bf[2 * tp][0], bf[2 * tp][1], bf[2 * tp + 1][0], bf[2 * tp + 1][1], addr);
            }
#pragma unroll
            for (int nt = 0; nt < 4; nt++)
                mma_f16(oacc[nt], a, bf[nt]);
        }

        if (j < 15) {
            int nxt = cur ^ 1;
            int r = tid >> 2, wv = tid & 3;
            *(uint4*)&Ks[nxt][r * 20 + wv * 4] = kreg;
#pragma unroll
            for (int i = 0; i < 2; i++) {
                int idx = i * 256 + tid;
                int p = idx >> 4, dp = idx & 15;
                Vs[nxt][(2 * dp) * 36 + p]     = __byte_perm(va[i], vbw[i], 0x5410);
                Vs[nxt][(2 * dp + 1) * 36 + p] = __byte_perm(va[i], vbw[i], 0x7632);
            }
        }
        __syncthreads();
    }

    float il0 = 1.f / l0, il1 = 1.f / l1;
    int n0 = bm + w * 16 + g;
    size_t ob0 = (size_t)(b * 1024 + n0) * 256;
    size_t ob1 = (size_t)(b * 1024 + n0 + 8) * 256;
#pragma unroll
    for (int nt = 0; nt < 4; nt++) {
        int wd = h * 16 + nt * 4 + tig;
        o[ob0 + wd] = h2u(__floats2half2_rn(oacc[nt][0] * il0, oacc[nt][1] * il0));
        o[ob1 + wd] = h2u(__floats2half2_rn(oacc[nt][2] * il1, oacc[nt][3] * il1));
    }
}

// ---------------- unpatchify ----------------------------------------------
__global__ void unpatch_kernel(const float* __restrict__ fin, float* __restrict__ img) {
    int idx = blockIdx.x * blockDim.x + threadIdx.x;
    if (idx >= 4 * 64 * 128 * 128) return;
    int W = idx & 127;
    int H = (idx >> 7) & 127;
    int c = (idx >> 14) & 63;
    int b = idx >> 20;
    int hh = H >> 2, p = H & 3, ww = W >> 2, qq = W & 3;
    img[idx] = fin[((size_t)(b * 1024 + hh * 32 + ww)) * 1024 + c * 16 + p * 4 + qq];
}

// ---------------- conv1: smem-tiled 3x3, 64->16 ch, ReLU -------------------
__global__ void conv1_kernel(const float* __restrict__ img, const float* __restrict__ w,
                             const float* __restrict__ bias, float* __restrict__ out) {
    __shared__ float patch[18 * 18];
    __shared__ float wsm[16 * 9];
    int b = blockIdx.y;
    int tile = blockIdx.x;
    int Y0 = (tile >> 3) * 16, X0 = (tile & 7) * 16;
    int tid = threadIdx.x;
    int ty = tid >> 4, tx = tid & 15;
    float acc[16];
#pragma unroll
    for (int oc = 0; oc < 16; oc++) acc[oc] = bias[oc];

    for (int ic = 0; ic < 64; ic++) {
        __syncthreads();
        const float* ip = img + ((size_t)(b * 64 + ic)) * 16384;
        for (int idx = tid; idx < 324; idx += 256) {
            int py = idx / 18, px = idx % 18;
            int gy = Y0 + py - 1, gx = X0 + px - 1;
            patch[idx] = (gy >= 0 && gy < 128 && gx >= 0 && gx < 128) ? ip[gy * 128 + gx] : 0.f;
        }
        if (tid < 144) wsm[tid] = w[(size_t)((tid / 9) * 64 + ic) * 9 + (tid % 9)];
        __syncthreads();
        float p[9];
#pragma unroll
        for (int ky = 0; ky < 3; ky++)
#pragma unroll
            for (int kx = 0; kx < 3; kx++)
                p[ky * 3 + kx] = patch[(ty + ky) * 18 + tx + kx];
#pragma unroll
        for (int oc = 0; oc < 16; oc++) {
            float a = 0.f;
#pragma unroll
            for (int t = 0; t < 9; t++) a += p[t] * wsm[oc * 9 + t];
            acc[oc] += a;
        }
    }
#pragma unroll
    for (int oc = 0; oc < 16; oc++)
        out[((size_t)(b * 16 + oc)) * 16384 + (Y0 + ty) * 128 + X0 + tx] = fmaxf(acc[oc], 0.f);
}

// ---------------- conv2: 3x3, 16->3 ch -------------------------------------
__global__ void conv2_kernel(const float* __restrict__ img, const float* __restrict__ w,
                             const float* __restrict__ bias, float* __restrict__ out) {
    int idx = blockIdx.x * blockDim.x + threadIdx.x;
    if (idx >= 4 * 3 * 128 * 128) return;
    int x = idx & 127, y = (idx >> 7) & 127;
    int oc = (idx >> 14) % 3, b = idx / (3 * 16384);
    float acc = bias[oc];
    for (int ic = 0; ic < 16; ic++) {
        const float* ip = img + ((size_t)(b * 16 + ic)) * 16384;
        const float* wp = w + (size_t)(oc * 16 + ic) * 9;
#pragma unroll
        for (int ky = 0; ky < 3; ky++) {
            int yy = y + ky - 1;
            if (yy < 0 || yy > 127) continue;
#pragma unroll
            for (int kx = 0; kx < 3; kx++) {
                int xx = x + kx - 1;
                if (xx < 0 || xx > 127) continue;
                acc += ip[yy * 128 + xx] * wp[ky * 3 + kx];
            }
        }
    }
    out[idx] = acc;
}

// ---------------- driver ---------------------------------------------------
extern "C" void kernel_launch(void* const* d_in, const int* in_sizes, int n_in,
                              void* d_out, int out_size) {
    const float* x_in  = (const float*)d_in[0];
    const float* qkv_w = (const float*)d_in[1];
    const float* qkv_b = (const float*)d_in[2];
    const float* proj_w= (const float*)d_in[3];
    const float* proj_b= (const float*)d_in[4];
    const float* nq_g  = (const float*)d_in[5];
    const float* nq_b  = (const float*)d_in[6];
    const float* nk_g  = (const float*)d_in[7];
    const float* nk_b  = (const float*)d_in[8];
    const float* n1_g  = (const float*)d_in[9];
    const float* n1_b  = (const float*)d_in[10];
    const float* n2_g  = (const float*)d_in[11];
    const float* n2_b  = (const float*)d_in[12];
    const float* fc1_w = (const float*)d_in[13];
    const float* fc1_b = (const float*)d_in[14];
    const float* fc2_w = (const float*)d_in[15];
    const float* fc2_b = (const float*)d_in[16];
    const float* fin_w = (const float*)d_in[17];
    const float* fin_b = (const float*)d_in[18];
    const float* c1_w  = (const float*)d_in[19];
    const float* c1_b  = (const float*)d_in[20];
    const float* c2_w  = (const float*)d_in[21];
    const float* c2_b  = (const float*)d_in[22];
    float* out = (float*)d_out;

    float *px, *px2, *pfin, *pimg, *pc1;
    uint32_t *plnh, *pmlph, *pq, *pk, *pv, *poh;
    uint32_t *pqkvw, *pprojw, *pfc1w, *pfc2w, *pfinw;
    cudaGetSymbolAddress((void**)&px,    g_x);
    cudaGetSymbolAddress((void**)&px2,   g_x2);
    cudaGetSymbolAddress((void**)&plnh,  g_lnh);
    cudaGetSymbolAddress((void**)&pmlph, g_mlph);
    cudaGetSymbolAddress((void**)&pq,    g_q);
    cudaGetSymbolAddress((void**)&pk,    g_k);
    cudaGetSymbolAddress((void**)&pv,    g_v);
    cudaGetSymbolAddress((void**)&poh,   g_oh);
    cudaGetSymbolAddress((void**)&pfin,  g_fin);
    cudaGetSymbolAddress((void**)&pimg,  g_img);
    cudaGetSymbolAddress((void**)&pc1,   g_c1);
    cudaGetSymbolAddress((void**)&pqkvw, g_qkvw);
    cudaGetSymbolAddress((void**)&pprojw,g_projw);
    cudaGetSymbolAddress((void**)&pfc1w, g_fc1w);
    cudaGetSymbolAddress((void**)&pfc2w, g_fc2w);
    cudaGetSymbolAddress((void**)&pfinw, g_finw);

    const int TOTW = 8*256*1536 + 8*256*512 + 8*256*2048 + 8*1024*512 + 256*1024;
    pack_all_kernel<<<(TOTW/4 + 255)/256, 256>>>(qkv_w, proj_w, fc1_w, fc2_w, fin_w,
                                                 pqkvw, pprojw, pfc1w, pfc2w, pfinw);
    add_pe_ln_kernel<<<512, 256>>>(x_in, n1_g, n1_b, px, plnh);

    for (int l = 0; l < 8; l++) {
        const uint32_t* qw  = pqkvw  + (size_t)l * 256 * 1536;
        const uint32_t* pw  = pprojw + (size_t)l * 256 * 512;
        const uint32_t* f1w = pfc1w  + (size_t)l * 256 * 2048;
        const uint32_t* f2w = pfc2w  + (size_t)l * 1024 * 512;
        const float* qb  = qkv_b  + (size_t)l * 1536;
        const float* pb  = proj_b + (size_t)l * 512;
        const float* f1b = fc1_b  + (size_t)l * 2048;
        const float* f2b = fc2_b  + (size_t)l * 512;

        sgemm_qkv_kernel<<<dim3(12, 32), 256>>>(plnh, qw, qb,
                                                nq_g + l * 32, nq_b + l * 32,
                                                nk_g + l * 32, nk_b + l * 32,
                                                pq, pk, pv);
        flash_kernel<<<dim3(8, 64), 256>>>(pq, pk, pv, poh);
        // proj + residual + LN2 fused
        sgemm_ln_kernel<<<128, 256>>>(poh, pw, pb, px, px2, plnh,
                                      n2_g + l * 512, n2_b + l * 512, 512, 1e-5f);
        sgemm_h16_kernel<<<dim3(16, 32), 256>>>(plnh, f1w, f1b, nullptr, pmlph,
                                                4096, 2048, 512, 2);
        // fc2 + residual + LN1(next layer) or final LN
        const float* ngam = (l < 7) ? (n1_g + (l + 1) * 512) : nullptr;
        const float* nbet = (l < 7) ? (n1_b + (l + 1) * 512) : nullptr;
        float neps = (l < 7) ? 1e-5f : 1e-6f;
        sgemm_ln_kernel<<<128, 256>>>(pmlph, f2w, f2b, px2, px, plnh,
                                      ngam, nbet, 2048, neps);
    }

    sgemm_h16_kernel<<<dim3(8, 32), 256>>>(plnh, pfinw, fin_b, pfin, nullptr,
                                           4096, 1024, 512, 0);
    unpatch_kernel<<<(4 * 64 * 128 * 128 + 255) / 256, 256>>>(pfin, pimg);
    conv1_kernel<<<dim3(64, 4), 256>>>(pimg, c1_w, c1_b, pc1);
    conv2_kernel<<<(4 * 3 * 128 * 128 + 255) / 256, 256>>>(pc1, c2_w, c2_b, out);
}

// round 16
// speedup vs baseline: 1.0520x; 1.0520x over previous
#include <cuda_runtime.h>
#include <cuda_fp16.h>
#include <math.h>
#include <stdint.h>

// ---------------- scratch (static device globals; no allocations) ----------
__device__ float    g_x   [4096*512];
__device__ float    g_x2  [4096*512];
__device__ uint32_t g_lnh [4096*256];     // LN output, half2 words
__device__ uint32_t g_mlph[4096*1024];    // fc1 output, half2 words
__device__ uint32_t g_q   [64*1024*16];   // half2 words, [bh][n][16]
__device__ uint32_t g_k   [64*1024*16];
__device__ uint32_t g_v   [64*1024*16];
__device__ uint32_t g_oh  [4096*256];     // flash output, half2 words
__device__ float    g_fin [4096*1024];
__device__ float    g_img [4*64*128*128];
__device__ float    g_c1  [4*16*128*128];
// packed weights (k-paired half2 words, [K/2][N])
__device__ uint32_t g_qkvw[8*256*1536];
__device__ uint32_t g_projw[8*256*512];
__device__ uint32_t g_fc1w[8*256*2048];
__device__ uint32_t g_fc2w[8*1024*512];
__device__ uint32_t g_finw[256*1024];

// ---------------- helpers --------------------------------------------------
__device__ __forceinline__ uint32_t h2u(__half2 h) {
    return *reinterpret_cast<uint32_t*>(&h);
}

__device__ __forceinline__ void mma_f16(float* c, const uint32_t* a, const uint32_t* b) {
    asm volatile(
        "mma.sync.aligned.m16n8k16.row.col.f32.f16.f16.f32 "
        "{%0,%1,%2,%3}, {%4,%5,%6,%7}, {%8,%9}, {%0,%1,%2,%3};"
        : "+f"(c[0]), "+f"(c[1]), "+f"(c[2]), "+f"(c[3])
        : "r"(a[0]), "r"(a[1]), "r"(a[2]), "r"(a[3]), "r"(b[0]), "r"(b[1]));
}

__device__ __forceinline__ void ldsm_x4(uint32_t& r0, uint32_t& r1, uint32_t& r2,
                                        uint32_t& r3, uint32_t addr) {
    asm volatile("ldmatrix.sync.aligned.m8n8.x4.shared.b16 {%0,%1,%2,%3}, [%4];"
        : "=r"(r0), "=r"(r1), "=r"(r2), "=r"(r3) : "r"(addr));
}

// ---------------- merged weight pack ---------------------------------------
__global__ void pack_all_kernel(const float* __restrict__ qkv_w, const float* __restrict__ proj_w,
                                const float* __restrict__ fc1_w, const float* __restrict__ fc2_w,
                                const float* __restrict__ fin_w,
                                uint32_t* __restrict__ qkvp, uint32_t* __restrict__ projp,
                                uint32_t* __restrict__ fc1p, uint32_t* __restrict__ fc2p,
                                uint32_t* __restrict__ finp) {
    const int S0 = 8*256*1536, S1 = S0 + 8*256*512, S2 = S1 + 8*256*2048,
              S3 = S2 + 8*1024*512, S4 = S3 + 256*1024;
    int t = (blockIdx.x * blockDim.x + threadIdx.x) * 4;
    if (t >= S4) return;
    const float* src; uint32_t* dst; int N; int base;
    if (t < S0)      { src = qkv_w;  dst = qkvp;  N = 1536; base = t; }
    else if (t < S1) { src = proj_w; dst = projp; N = 512;  base = t - S0; }
    else if (t < S2) { src = fc1_w;  dst = fc1p;  N = 2048; base = t - S1; }
    else if (t < S3) { src = fc2_w;  dst = fc2p;  N = 512;  base = t - S2; }
    else             { src = fin_w;  dst = finp;  N = 1024; base = t - S3; }
    int p = base / N, n = base - p * N;
    float4 r0 = *(const float4*)&src[(size_t)(2 * p) * N + n];
    float4 r1 = *(const float4*)&src[(size_t)(2 * p + 1) * N + n];
    uint4 o;
    o.x = h2u(__floats2half2_rn(r0.x, r1.x));
    o.y = h2u(__floats2half2_rn(r0.y, r1.y));
    o.z = h2u(__floats2half2_rn(r0.z, r1.z));
    o.w = h2u(__floats2half2_rn(r0.w, r1.w));
    *(uint4*)&dst[base] = o;
}

// ---------------- pos-embed add + LN (layer 0), warp per row ---------------
__global__ void add_pe_ln_kernel(const float* __restrict__ x,
                                 const float* __restrict__ gam, const float* __restrict__ bet,
                                 float* __restrict__ outF, uint32_t* __restrict__ outH) {
    int row = (blockIdx.x * blockDim.x + threadIdx.x) >> 5;
    int lane = threadIdx.x & 31;
    if (row >= 4096) return;
    int p = row & 1023;
    int pi = p >> 5, pj = p & 31;
    const float4* xp = (const float4*)(x + (size_t)row * 512);
    float4 v[4];
    float s = 0.f;
#pragma unroll
    for (int i = 0; i < 4; i++) {
        v[i] = xp[lane + i * 32];
        int c0 = (lane + i * 32) * 4;
        float* vf = (float*)&v[i];
#pragma unroll
        for (int j = 0; j < 4; j++) {
            int c = c0 + j;
            int pos = (c < 256) ? pj : pi;
            int cc = c & 255;
            int m = cc & 127;
            float om = __expf(-(float)m * 0.0719558141f);
            float a = (float)pos * om;
            vf[j] += (cc < 128) ? sinf(a) : cosf(a);
        }
        s += v[i].x + v[i].y + v[i].z + v[i].w;
    }
#pragma unroll
    for (int o = 16; o > 0; o >>= 1) s += __shfl_xor_sync(0xffffffffu, s, o);
    float mu = s * (1.f / 512.f);
    float sq = 0.f;
#pragma unroll
    for (int i = 0; i < 4; i++) {
        float dx = v[i].x - mu, dy = v[i].y - mu, dz = v[i].z - mu, dw = v[i].w - mu;
        sq += dx * dx + dy * dy + dz * dz + dw * dw;
    }
#pragma unroll
    for (int o = 16; o > 0; o >>= 1) sq += __shfl_xor_sync(0xffffffffu, sq, o);
    float rstd = rsqrtf(sq * (1.f / 512.f) + 1e-5f);
    float4* fp = (float4*)(outF + (size_t)row * 512);
    uint32_t* op = outH + (size_t)row * 256;
#pragma unroll
    for (int i = 0; i < 4; i++) {
        fp[lane + i * 32] = v[i];
        float4 gg = ((const float4*)gam)[lane + i * 32];
        float4 bb = ((const float4*)bet)[lane + i * 32];
        float y0 = (v[i].x - mu) * rstd * gg.x + bb.x;
        float y1 = (v[i].y - mu) * rstd * gg.y + bb.y;
        float y2 = (v[i].z - mu) * rstd * gg.z + bb.z;
        float y3 = (v[i].w - mu) * rstd * gg.w + bb.w;
        uint2 wds;
        wds.x = h2u(__floats2half2_rn(y0, y1));
        wds.y = h2u(__floats2half2_rn(y2, y3));
        *(uint2*)&op[2 * (lane + i * 32)] = wds;
    }
}

// ---------------- layernorm: warp/row, fp32 in -> half2 out ---------------
__global__ void ln_kernel(const float* __restrict__ in, const float* __restrict__ g,
                          const float* __restrict__ b, uint32_t* __restrict__ out,
                          float eps) {
    int row = (blockIdx.x * blockDim.x + threadIdx.x) >> 5;
    int lane = threadIdx.x & 31;
    if (row >= 4096) return;
    const float4* x = (const float4*)(in + (size_t)row * 512);
    float4 v[4];
    float s = 0.f;
#pragma unroll
    for (int i = 0; i < 4; i++) {
        v[i] = x[lane + i * 32];
        s += v[i].x + v[i].y + v[i].z + v[i].w;
    }
#pragma unroll
    for (int o = 16; o > 0; o >>= 1) s += __shfl_xor_sync(0xffffffffu, s, o);
    float mu = s * (1.f / 512.f);
    float sq = 0.f;
#pragma unroll
    for (int i = 0; i < 4; i++) {
        float dx = v[i].x - mu, dy = v[i].y - mu, dz = v[i].z - mu, dw = v[i].w - mu;
        sq += dx * dx + dy * dy + dz * dz + dw * dw;
    }
#pragma unroll
    for (int o = 16; o > 0; o >>= 1) sq += __shfl_xor_sync(0xffffffffu, sq, o);
    float rstd = rsqrtf(sq * (1.f / 512.f) + eps);
    uint32_t* op = out + (size_t)row * 256;
#pragma unroll
    for (int i = 0; i < 4; i++) {
        float4 y;
        y.x = (v[i].x - mu) * rstd; y.y = (v[i].y - mu) * rstd;
        y.z = (v[i].z - mu) * rstd; y.w = (v[i].w - mu) * rstd;
        if (g) {
            float4 gg = ((const float4*)g)[lane + i * 32];
            float4 bb = ((const float4*)b)[lane + i * 32];
            y.x = y.x * gg.x + bb.x; y.y = y.y * gg.y + bb.y;
            y.z = y.z * gg.z + bb.z; y.w = y.w * gg.w + bb.w;
        }
        uint2 wds;
        wds.x = h2u(__floats2half2_rn(y.x, y.y));
        wds.y = h2u(__floats2half2_rn(y.z, y.w));
        *(uint2*)&op[2 * (lane + i * 32)] = wds;
    }
}

// ---------------- fp16-operand GEMM, 128x128 tile (ldmatrix A) -------------
// mode 0: Cf=acc+bias; 1: Cf=acc+bias+res; 2: Ch=half(GELU(acc+bias)).
__global__ void __launch_bounds__(256) sgemm_h16_kernel(
        const uint32_t* __restrict__ A, const uint32_t* __restrict__ B,
        const float* __restrict__ bias, const float* __restrict__ res,
        float* __restrict__ Cf, uint32_t* __restrict__ Ch,
        int M, int N, int K, int mode) {
    __shared__ uint32_t As[128 * 20];
    __shared__ uint32_t Bs[16 * 136];
    int tid = threadIdx.x;
    int w = tid >> 5, lane = tid & 31;
    int g = lane >> 2, tig = lane & 3;
    int warp_m = w & 1, warp_n = w >> 1;
    int bm = blockIdx.y * 128, bn = blockIdx.x * 128;
    int Kw = K >> 1;

    int arow[2], ac4[2], bp[2], bn4[2];
#pragma unroll
    for (int i = 0; i < 2; i++) {
        int idx = i * 256 + tid;
        arow[i] = idx >> 2;  ac4[i] = idx & 3;
        bp[i]   = idx >> 5;  bn4[i] = idx & 31;
    }
    uint32_t as_base = (uint32_t)__cvta_generic_to_shared(As);
    uint32_t a_addr = as_base + (((warp_m * 64 + (lane & 15)) * 20 + (lane >> 4) * 4) << 2);

    float acc[4][4][4] = {};
    uint4 pa[2], pb[2];
#pragma unroll
    for (int i = 0; i < 2; i++) {
        pa[i] = *(const uint4*)&A[(size_t)(bm + arow[i]) * Kw + ac4[i] * 4];
        pb[i] = *(const uint4*)&B[(size_t)bp[i] * N + bn + bn4[i] * 4];
    }

    for (int k0 = 0; k0 < K; k0 += 32) {
#pragma unroll
        for (int i = 0; i < 2; i++) {
            *(uint4*)&As[arow[i] * 20 + ac4[i] * 4] = pa[i];
            *(uint4*)&Bs[bp[i] * 136 + bn4[i] * 4] = pb[i];
        }
        __syncthreads();
        if (k0 + 32 < K) {
            int kw0 = (k0 + 32) >> 1;
#pragma unroll
            for (int i = 0; i < 2; i++) {
                pa[i] = *(const uint4*)&A[(size_t)(bm + arow[i]) * Kw + kw0 + ac4[i] * 4];
                pb[i] = *(const uint4*)&B[(size_t)(kw0 + bp[i]) * N + bn + bn4[i] * 4];
            }
        }
#pragma unroll
        for (int ks = 0; ks < 2; ks++) {
            int kw = ks * 8;
            uint32_t a[4][4], b[4][2];
#pragma unroll
            for (int mt = 0; mt < 4; mt++)
                ldsm_x4(a[mt][0], a[mt][1], a[mt][2], a[mt][3],
                        a_addr + mt * 1280 + ks * 32);
#pragma unroll
            for (int nt = 0; nt < 4; nt++) {
                int nc = warp_n * 32 + nt * 8;
                b[nt][0] = Bs[(kw + tig) * 136 + nc + g];
                b[nt][1] = Bs[(kw + 4 + tig) * 136 + nc + g];
            }
#pragma unroll
            for (int mt = 0; mt < 4; mt++)
#pragma unroll
                for (int nt = 0; nt < 4; nt++)
                    mma_f16(acc[mt][nt], a[mt], b[nt]);
        }
        __syncthreads();
    }

#pragma unroll
    for (int mt = 0; mt < 4; mt++) {
#pragma unroll
        for (int nt = 0; nt < 4; nt++) {
            int row0 = bm + warp_m * 64 + mt * 16 + g;
            int col0 = bn + warp_n * 32 + nt * 8 + 2 * tig;
            if (mode == 2) {
#pragma unroll
                for (int rh = 0; rh < 2; rh++) {
                    int row = row0 + rh * 8;
                    float v0 = acc[mt][nt][rh * 2]     + bias[col0];
                    float v1 = acc[mt][nt][rh * 2 + 1] + bias[col0 + 1];
                    v0 = 0.5f * v0 * (1.f + erff(v0 * 0.70710678118654752f));
                    v1 = 0.5f * v1 * (1.f + erff(v1 * 0.70710678118654752f));
                    Ch[(size_t)row * (N >> 1) + (col0 >> 1)] = h2u(__floats2half2_rn(v0, v1));
                }
            } else {
#pragma unroll
                for (int i = 0; i < 4; i++) {
                    int row = row0 + (i >> 1) * 8;
                    int col = col0 + (i & 1);
                    float v = acc[mt][nt][i] + bias[col];
                    if (mode == 1) v += res[(size_t)row * N + col];
                    Cf[(size_t)row * N + col] = v;
                }
            }
        }
    }
}

// ---------------- fp16-operand GEMM, 128x64 tile (for N=512 GEMMs) --------
// Always: Cf = acc + bias + res. Warps 4(M) x 2(N), warp tile 32x32.
__global__ void __launch_bounds__(256) sgemm_h16_n64_kernel(
        const uint32_t* __restrict__ A, const uint32_t* __restrict__ B,
        const float* __restrict__ bias, const float* __restrict__ res,
        float* __restrict__ Cf, int M, int N, int K) {
    __shared__ uint32_t As[128 * 20];
    __shared__ uint32_t Bs[16 * 72];
    int tid = threadIdx.x;
    int w = tid >> 5, lane = tid & 31;
    int g = lane >> 2, tig = lane & 3;
    int warp_m = w & 3, warp_n = w >> 2;
    int bm = blockIdx.y * 128, bn = blockIdx.x * 64;
    int Kw = K >> 1;

    int arow[2], ac4[2];
#pragma unroll
    for (int i = 0; i < 2; i++) {
        int idx = i * 256 + tid;
        arow[i] = idx >> 2;  ac4[i] = idx & 3;
    }
    int bp = tid >> 4, bn4 = tid & 15;
    uint32_t as_base = (uint32_t)__cvta_generic_to_shared(As);
    uint32_t a_addr = as_base + (((warp_m * 32 + (lane & 15)) * 20 + (lane >> 4) * 4) << 2);

    float acc[2][4][4] = {};
    uint4 pa[2], pb;
#pragma unroll
    for (int i = 0; i < 2; i++)
        pa[i] = *(const uint4*)&A[(size_t)(bm + arow[i]) * Kw + ac4[i] * 4];
    pb = *(const uint4*)&B[(size_t)bp * N + bn + bn4 * 4];

    for (int k0 = 0; k0 < K; k0 += 32) {
#pragma unroll
        for (int i = 0; i < 2; i++)
            *(uint4*)&As[arow[i] * 20 + ac4[i] * 4] = pa[i];
        *(uint4*)&Bs[bp * 72 + bn4 * 4] = pb;
        __syncthreads();
        if (k0 + 32 < K) {
            int kw0 = (k0 + 32) >> 1;
#pragma unroll
            for (int i = 0; i < 2; i++)
                pa[i] = *(const uint4*)&A[(size_t)(bm + arow[i]) * Kw + kw0 + ac4[i] * 4];
            pb = *(const uint4*)&B[(size_t)(kw0 + bp) * N + bn + bn4 * 4];
        }
#pragma unroll
        for (int ks = 0; ks < 2; ks++) {
            int kw = ks * 8;
            uint32_t a[2][4], b[4][2];
#pragma unroll
            for (int mt = 0; mt < 2; mt++)
                ldsm_x4(a[mt][0], a[mt][1], a[mt][2], a[mt][3],
                        a_addr + mt * 1280 + ks * 32);
#pragma unroll
            for (int nt = 0; nt < 4; nt++) {
                int nc = warp_n * 32 + nt * 8;
                b[nt][0] = Bs[(kw + tig) * 72 + nc + g];
                b[nt][1] = Bs[(kw + 4 + tig) * 72 + nc + g];
            }
#pragma unroll
            for (int mt = 0; mt < 2; mt++)
#pragma unroll
                for (int nt = 0; nt < 4; nt++)
                    mma_f16(acc[mt][nt], a[mt], b[nt]);
        }
        __syncthreads();
    }

#pragma unroll
    for (int mt = 0; mt < 2; mt++) {
#pragma unroll
        for (int nt = 0; nt < 4; nt++) {
            int row0 = bm + warp_m * 32 + mt * 16 + g;
            int col0 = bn + warp_n * 32 + nt * 8 + 2 * tig;
#pragma unroll
            for (int i = 0; i < 4; i++) {
                int row = row0 + (i >> 1) * 8;
                int col = col0 + (i & 1);
                Cf[(size_t)row * N + col] = acc[mt][nt][i] + bias[col] + res[(size_t)row * N + col];
            }
        }
    }
}

// ---------------- QKV GEMM (fp16 operands, ldmatrix) + split + head-LN ----
__global__ void __launch_bounds__(256) sgemm_qkv_kernel(
        const uint32_t* __restrict__ A, const uint32_t* __restrict__ B,
        const float* __restrict__ bias,
        const float* __restrict__ nqg, const float* __restrict__ nqb,
        const float* __restrict__ nkg, const float* __restrict__ nkb,
        uint32_t* __restrict__ q, uint32_t* __restrict__ k,
        uint32_t* __restrict__ v) {
    const int N = 1536, K = 512, Kw = 256;
    __shared__ uint32_t As[128 * 20];
    __shared__ uint32_t Bs[16 * 136];
    int tid = threadIdx.x;
    int w = tid >> 5, lane = tid & 31;
    int g = lane >> 2, tig = lane & 3;
    int warp_m = w & 1, warp_n = w >> 1;
    int bm = blockIdx.y * 128, bn = blockIdx.x * 128;

    int arow[2], ac4[2], bp[2], bn4[2];
#pragma unroll
    for (int i = 0; i < 2; i++) {
        int idx = i * 256 + tid;
        arow[i] = idx >> 2;  ac4[i] = idx & 3;
        bp[i]   = idx >> 5;  bn4[i] = idx & 31;
    }
    uint32_t as_base = (uint32_t)__cvta_generic_to_shared(As);
    uint32_t a_addr = as_base + (((warp_m * 64 + (lane & 15)) * 20 + (lane >> 4) * 4) << 2);

    float acc[4][4][4] = {};
    uint4 pa[2], pb[2];
#pragma unroll
    for (int i = 0; i < 2; i++) {
        pa[i] = *(const uint4*)&A[(size_t)(bm + arow[i]) * Kw + ac4[i] * 4];
        pb[i] = *(const uint4*)&B[(size_t)bp[i] * N + bn + bn4[i] * 4];
    }

    for (int k0 = 0; k0 < K; k0 += 32) {
#pragma unroll
        for (int i = 0; i < 2; i++) {
            *(uint4*)&As[arow[i] * 20 + ac4[i] * 4] = pa[i];
            *(uint4*)&Bs[bp[i] * 136 + bn4[i] * 4] = pb[i];
        }
        __syncthreads();
        if (k0 + 32 < K) {
            int kw0 = (k0 + 32) >> 1;
#pragma unroll
            for (int i = 0; i < 2; i++) {
                pa[i] = *(const uint4*)&A[(size_t)(bm + arow[i]) * Kw + kw0 + ac4[i] * 4];
                pb[i] = *(const uint4*)&B[(size_t)(kw0 + bp[i]) * N + bn + bn4[i] * 4];
            }
        }
#pragma unroll
        for (int ks = 0; ks < 2; ks++) {
            int kw = ks * 8;
            uint32_t a[4][4], b[4][2];
#pragma unroll
            for (int mt = 0; mt < 4; mt++)
                ldsm_x4(a[mt][0], a[mt][1], a[mt][2], a[mt][3],
                        a_addr + mt * 1280 + ks * 32);
#pragma unroll
            for (int nt = 0; nt < 4; nt++) {
                int nc = warp_n * 32 + nt * 8;
                b[nt][0] = Bs[(kw + tig) * 136 + nc + g];
                b[nt][1] = Bs[(kw + 4 + tig) * 136 + nc + g];
            }
#pragma unroll
            for (int mt = 0; mt < 4; mt++)
#pragma unroll
                for (int nt = 0; nt < 4; nt++)
                    mma_f16(acc[mt][nt], a[mt], b[nt]);
        }
        __syncthreads();
    }

    int colbase = bn + warp_n * 32;
    int sec = colbase >> 9;
    int h = (colbase & 511) >> 5;
    const float sc = 0.17677669529663689f * 1.4426950408889634f;
    const float* gam = (sec == 0) ? nqg : nkg;
    const float* bet = (sec == 0) ? nqb : nkb;
    uint32_t* dst = (sec == 0) ? q : ((sec == 1) ? k : v);

#pragma unroll
    for (int mt = 0; mt < 4; mt++) {
#pragma unroll
        for (int rh = 0; rh < 2; rh++) {
            int row = bm + warp_m * 64 + mt * 16 + g + rh * 8;
            int bb = row >> 10, n = row & 1023;
            size_t offw = ((size_t)(bb * 16 + h) * 1024 + n) * 16;
            float vv[8];
#pragma unroll
            for (int nt = 0; nt < 4; nt++) {
#pragma unroll
                for (int j = 0; j < 2; j++) {
                    int col = colbase + nt * 8 + 2 * tig + j;
                    vv[nt * 2 + j] = acc[mt][nt][rh * 2 + j] + bias[col];
                }
            }
            if (sec == 2) {
#pragma unroll
                for (int nt = 0; nt < 4; nt++)
                    dst[offw + nt * 4 + tig] = h2u(__floats2half2_rn(vv[nt * 2], vv[nt * 2 + 1]));
            } else {
                float s = 0.f;
#pragma unroll
                for (int t = 0; t < 8; t++) s += vv[t];
                s += __shfl_xor_sync(0xffffffffu, s, 1);
                s += __shfl_xor_sync(0xffffffffu, s, 2);
                float mu = s * (1.f / 32.f);
                float sq = 0.f;
#pragma unroll
                for (int t = 0; t < 8; t++) { float d = vv[t] - mu; sq += d * d; }
                sq += __shfl_xor_sync(0xffffffffu, sq, 1);
                sq += __shfl_xor_sync(0xffffffffu, sq, 2);
                float rstd = rsqrtf(sq * (1.f / 32.f) + 1e-5f);
#pragma unroll
                for (int nt = 0; nt < 4; nt++) {
                    int d = nt * 8 + 2 * tig;
                    float y0 = (vv[nt * 2] - mu) * rstd * gam[d] + bet[d];
                    float y1 = (vv[nt * 2 + 1] - mu) * rstd * gam[d + 1] + bet[d + 1];
                    if (sec == 0) { y0 *= sc; y1 *= sc; }
                    dst[offw + nt * 4 + tig] = h2u(__floats2half2_rn(y0, y1));
                }
            }
        }
    }
}

// ---------------- flash attention (fp16, register P, ldmatrix K/V) --------
__global__ void __launch_bounds__(256, 3) flash_kernel(
        const uint32_t* __restrict__ q, const uint32_t* __restrict__ k,
        const uint32_t* __restrict__ v, uint32_t* __restrict__ o) {
    __shared__ uint32_t Qs[128 * 20];
    __shared__ uint32_t Ks[2][64 * 20];
    __shared__ uint32_t Vs[2][32 * 36];

    int bh = blockIdx.y;
    int bm = blockIdx.x * 128;
    int b = bh >> 4, h = bh & 15;
    int tid = threadIdx.x;
    int w = tid >> 5, lane = tid & 31;
    int g = lane >> 2, tig = lane & 3;

    const uint32_t* qb = q + ((size_t)bh * 1024 + bm) * 16;
    const uint32_t* kb = k + (size_t)bh * 1024 * 16;
    const uint32_t* vb = v + (size_t)bh * 1024 * 16;

#pragma unroll
    for (int i = 0; i < 2; i++) {
        int idx = i * 256 + tid;
        int r = idx >> 2, wv = idx & 3;
        *(uint4*)&Qs[r * 20 + wv * 4] = *(const uint4*)&qb[r * 16 + wv * 4];
    }
    {
        int r = tid >> 2, wv = tid & 3;
        *(uint4*)&Ks[0][r * 20 + wv * 4] = *(const uint4*)&kb[r * 16 + wv * 4];
#pragma unroll
        for (int i = 0; i < 2; i++) {
            int idx = i * 256 + tid;
            int p = idx >> 4, dp = idx & 15;
            uint32_t a = vb[(size_t)(2 * p) * 16 + dp];
            uint32_t bw = vb[(size_t)(2 * p + 1) * 16 + dp];
            Vs[0][(2 * dp) * 36 + p]     = __byte_perm(a, bw, 0x5410);
            Vs[0][(2 * dp + 1) * 36 + p] = __byte_perm(a, bw, 0x7632);
        }
    }
    __syncthreads();

    int frow = (lane & 7) + ((lane & 16) >> 1);
    int fcol = (lane & 8) >> 1;
    uint32_t qs_base = (uint32_t)__cvta_generic_to_shared(Qs);
    uint32_t ks_base0 = (uint32_t)__cvta_generic_to_shared(&Ks[0][0]);
    uint32_t vs_base0 = (uint32_t)__cvta_generic_to_shared(&Vs[0][0]);

    uint32_t qa[2][4];
    {
        uint32_t qaddr = qs_base + (((w * 16 + (lane & 15)) * 20 + (lane >> 4) * 4) << 2);
        ldsm_x4(qa[0][0], qa[0][1], qa[0][2], qa[0][3], qaddr);
        ldsm_x4(qa[1][0], qa[1][1], qa[1][2], qa[1][3], qaddr + 32);
    }

    float oacc[4][4] = {};
    float m0 = -1e30f, m1 = -1e30f, l0 = 0.f, l1 = 0.f;

    for (int j = 0; j < 16; j++) {
        int cur = j & 1;
        uint32_t ks_b = ks_base0 + cur * (64 * 20 * 4);
        uint32_t vs_b = vs_base0 + cur * (32 * 36 * 4);
        uint4 kreg;
        uint32_t va[2], vbw[2];
        if (j < 15) {
            int r = tid >> 2, wv = tid & 3;
            kreg = *(const uint4*)&kb[(size_t)((j + 1) * 64 + r) * 16 + wv * 4];
#pragma unroll
            for (int i = 0; i < 2; i++) {
                int idx = i * 256 + tid;
                int p = idx >> 4, dp = idx & 15;
                va[i]  = vb[(size_t)((j + 1) * 64 + 2 * p) * 16 + dp];
                vbw[i] = vb[(size_t)((j + 1) * 64 + 2 * p + 1) * 16 + dp];
            }
        }

        float s[8][4] = {};
#pragma unroll
        for (int ks = 0; ks < 2; ks++) {
            uint32_t bf[8][2];
#pragma unroll
            for (int tp = 0; tp < 4; tp++) {
                uint32_t addr = ks_b + (((tp * 16 + frow) * 20 + ks * 8 + fcol) << 2);
                ldsm_x4(bf[2 * tp][0], bf[2 * tp][1], bf[2 * tp + 1][0], bf[2 * tp + 1][1], addr);
            }
#pragma unroll
            for (int nt = 0; nt < 8; nt++)
                mma_f16(s[nt], qa[ks], bf[nt]);
        }

        float rm0 = -1e30f, rm1 = -1e30f;
#pragma unroll
        for (int nt = 0; nt < 8; nt++) {
            rm0 = fmaxf(rm0, fmaxf(s[nt][0], s[nt][1]));
            rm1 = fmaxf(rm1, fmaxf(s[nt][2], s[nt][3]));
        }
        rm0 = fmaxf(rm0, __shfl_xor_sync(0xffffffffu, rm0, 1));
        rm0 = fmaxf(rm0, __shfl_xor_sync(0xffffffffu, rm0, 2));
        rm1 = fmaxf(rm1, __shfl_xor_sync(0xffffffffu, rm1, 1));
        rm1 = fmaxf(rm1, __shfl_xor_sync(0xffffffffu, rm1, 2));
        float nm0 = fmaxf(m0, rm0), nm1 = fmaxf(m1, rm1);
        float al0 = exp2f(m0 - nm0), al1 = exp2f(m1 - nm1);
        float rs0 = 0.f, rs1 = 0.f;
#pragma unroll
        for (int nt = 0; nt < 8; nt++) {
            s[nt][0] = exp2f(s[nt][0] - nm0);
            s[nt][1] = exp2f(s[nt][1] - nm0);
            s[nt][2] = exp2f(s[nt][2] - nm1);
            s[nt][3] = exp2f(s[nt][3] - nm1);
            rs0 += s[nt][0] + s[nt][1];
            rs1 += s[nt][2] + s[nt][3];
        }
        rs0 += __shfl_xor_sync(0xffffffffu, rs0, 1);
        rs0 += __shfl_xor_sync(0xffffffffu, rs0, 2);
        rs1 += __shfl_xor_sync(0xffffffffu, rs1, 1);
        rs1 += __shfl_xor_sync(0xffffffffu, rs1, 2);
        l0 = l0 * al0 + rs0;
        l1 = l1 * al1 + rs1;
        m0 = nm0; m1 = nm1;
#pragma unroll
        for (int nt = 0; nt < 4; nt++) {
            oacc[nt][0] *= al0; oacc[nt][1] *= al0;
            oacc[nt][2] *= al1; oacc[nt][3] *= al1;
        }

#pragma unroll
        for (int ks2 = 0; ks2 < 4; ks2++) {
            uint32_t a[4];
            a[0] = h2u(__floats2half2_rn(s[2 * ks2][0],     s[2 * ks2][1]));
            a[1] = h2u(__floats2half2_rn(s[2 * ks2][2],     s[2 * ks2][3]));
            a[2] = h2u(__floats2half2_rn(s[2 * ks2 + 1][0], s[2 * ks2 + 1][1]));
            a[3] = h2u(__floats2half2_rn(s[2 * ks2 + 1][2], s[2 * ks2 + 1][3]));
            uint32_t bf[4][2];
#pragma unroll
            for (int tp = 0; tp < 2; tp++) {
                uint32_t addr = vs_b + (((tp * 16 + frow) * 36 + ks2 * 8 + fcol) << 2);
                ldsm_x4(bf[2 * tp][0], bf[2 * tp][1], bf[2 * tp + 1][0], bf[2 * tp + 1][1], addr);
            }
#pragma unroll
            for (int nt = 0; nt < 4; nt++)
                mma_f16(oacc[nt], a, bf[nt]);
        }

        if (j < 15) {
            int nxt = cur ^ 1;
            int r = tid >> 2, wv = tid & 3;
            *(uint4*)&Ks[nxt][r * 20 + wv * 4] = kreg;
#pragma unroll
            for (int i = 0; i < 2; i++) {
                int idx = i * 256 + tid;
                int p = idx >> 4, dp = idx & 15;
                Vs[nxt][(2 * dp) * 36 + p]     = __byte_perm(va[i], vbw[i], 0x5410);
                Vs[nxt][(2 * dp + 1) * 36 + p] = __byte_perm(va[i], vbw[i], 0x7632);
            }
        }
        __syncthreads();
    }

    float il0 = 1.f / l0, il1 = 1.f / l1;
    int n0 = bm + w * 16 + g;
    size_t ob0 = (size_t)(b * 1024 + n0) * 256;
    size_t ob1 = (size_t)(b * 1024 + n0 + 8) * 256;
#pragma unroll
    for (int nt = 0; nt < 4; nt++) {
        int wd = h * 16 + nt * 4 + tig;
        o[ob0 + wd] = h2u(__floats2half2_rn(oacc[nt][0] * il0, oacc[nt][1] * il0));
        o[ob1 + wd] = h2u(__floats2half2_rn(oacc[nt][2] * il1, oacc[nt][3] * il1));
    }
}

// ---------------- unpatchify ----------------------------------------------
__global__ void unpatch_kernel(const float* __restrict__ fin, float* __restrict__ img) {
    int idx = blockIdx.x * blockDim.x + threadIdx.x;
    if (idx >= 4 * 64 * 128 * 128) return;
    int W = idx & 127;
    int H = (idx >> 7) & 127;
    int c = (idx >> 14) & 63;
    int b = idx >> 20;
    int hh = H >> 2, p = H & 3, ww = W >> 2, qq = W & 3;
    img[idx] = fin[((size_t)(b * 1024 + hh * 32 + ww)) * 1024 + c * 16 + p * 4 + qq];
}

// ---------------- conv1: smem-tiled 3x3, 64->16 ch, ReLU -------------------
__global__ void conv1_kernel(const float* __restrict__ img, const float* __restrict__ w,
                             const float* __restrict__ bias, float* __restrict__ out) {
    __shared__ float patch[18 * 18];
    __shared__ float wsm[16 * 9];
    int b = blockIdx.y;
    int tile = blockIdx.x;
    int Y0 = (tile >> 3) * 16, X0 = (tile & 7) * 16;
    int tid = threadIdx.x;
    int ty = tid >> 4, tx = tid & 15;
    float acc[16];
#pragma unroll
    for (int oc = 0; oc < 16; oc++) acc[oc] = bias[oc];

    for (int ic = 0; ic < 64; ic++) {
        __syncthreads();
        const float* ip = img + ((size_t)(b * 64 + ic)) * 16384;
        for (int idx = tid; idx < 324; idx += 256) {
            int py = idx / 18, px = idx % 18;
            int gy = Y0 + py - 1, gx = X0 + px - 1;
            patch[idx] = (gy >= 0 && gy < 128 && gx >= 0 && gx < 128) ? ip[gy * 128 + gx] : 0.f;
        }
        if (tid < 144) wsm[tid] = w[(size_t)((tid / 9) * 64 + ic) * 9 + (tid % 9)];
        __syncthreads();
        float p[9];
#pragma unroll
        for (int ky = 0; ky < 3; ky++)
#pragma unroll
            for (int kx = 0; kx < 3; kx++)
                p[ky * 3 + kx] = patch[(ty + ky) * 18 + tx + kx];
#pragma unroll
        for (int oc = 0; oc < 16; oc++) {
            float a = 0.f;
#pragma unroll
            for (int t = 0; t < 9; t++) a += p[t] * wsm[oc * 9 + t];
            acc[oc] += a;
        }
    }
#pragma unroll
    for (int oc = 0; oc < 16; oc++)
        out[((size_t)(b * 16 + oc)) * 16384 + (Y0 + ty) * 128 + X0 + tx] = fmaxf(acc[oc], 0.f);
}

// ---------------- conv2: 3x3, 16->3 ch -------------------------------------
__global__ void conv2_kernel(const float* __restrict__ img, const float* __restrict__ w,
                             const float* __restrict__ bias, float* __restrict__ out) {
    int idx = blockIdx.x * blockDim.x + threadIdx.x;
    if (idx >= 4 * 3 * 128 * 128) return;
    int x = idx & 127, y = (idx >> 7) & 127;
    int oc = (idx >> 14) % 3, b = idx / (3 * 16384);
    float acc = bias[oc];
    for (int ic = 0; ic < 16; ic++) {
        const float* ip = img + ((size_t)(b * 16 + ic)) * 16384;
        const float* wp = w + (size_t)(oc * 16 + ic) * 9;
#pragma unroll
        for (int ky = 0; ky < 3; ky++) {
            int yy = y + ky - 1;
            if (yy < 0 || yy > 127) continue;
#pragma unroll
            for (int kx = 0; kx < 3; kx++) {
                int xx = x + kx - 1;
                if (xx < 0 || xx > 127) continue;
                acc += ip[yy * 128 + xx] * wp[ky * 3 + kx];
            }
        }
    }
    out[idx] = acc;
}

// ---------------- driver ---------------------------------------------------
extern "C" void kernel_launch(void* const* d_in, const int* in_sizes, int n_in,
                              void* d_out, int out_size) {
    const float* x_in  = (const float*)d_in[0];
    const float* qkv_w = (const float*)d_in[1];
    const float* qkv_b = (const float*)d_in[2];
    const float* proj_w= (const float*)d_in[3];
    const float* proj_b= (const float*)d_in[4];
    const float* nq_g  = (const float*)d_in[5];
    const float* nq_b  = (const float*)d_in[6];
    const float* nk_g  = (const float*)d_in[7];
    const float* nk_b  = (const float*)d_in[8];
    const float* n1_g  = (const float*)d_in[9];
    const float* n1_b  = (const float*)d_in[10];
    const float* n2_g  = (const float*)d_in[11];
    const float* n2_b  = (const float*)d_in[12];
    const float* fc1_w = (const float*)d_in[13];
    const float* fc1_b = (const float*)d_in[14];
    const float* fc2_w = (const float*)d_in[15];
    const float* fc2_b = (const float*)d_in[16];
    const float* fin_w = (const float*)d_in[17];
    const float* fin_b = (const float*)d_in[18];
    const float* c1_w  = (const float*)d_in[19];
    const float* c1_b  = (const float*)d_in[20];
    const float* c2_w  = (const float*)d_in[21];
    const float* c2_b  = (const float*)d_in[22];
    float* out = (float*)d_out;

    float *px, *px2, *pfin, *pimg, *pc1;
    uint32_t *plnh, *pmlph, *pq, *pk, *pv, *poh;
    uint32_t *pqkvw, *pprojw, *pfc1w, *pfc2w, *pfinw;
    cudaGetSymbolAddress((void**)&px,    g_x);
    cudaGetSymbolAddress((void**)&px2,   g_x2);
    cudaGetSymbolAddress((void**)&plnh,  g_lnh);
    cudaGetSymbolAddress((void**)&pmlph, g_mlph);
    cudaGetSymbolAddress((void**)&pq,    g_q);
    cudaGetSymbolAddress((void**)&pk,    g_k);
    cudaGetSymbolAddress((void**)&pv,    g_v);
    cudaGetSymbolAddress((void**)&poh,   g_oh);
    cudaGetSymbolAddress((void**)&pfin,  g_fin);
    cudaGetSymbolAddress((void**)&pimg,  g_img);
    cudaGetSymbolAddress((void**)&pc1,   g_c1);
    cudaGetSymbolAddress((void**)&pqkvw, g_qkvw);
    cudaGetSymbolAddress((void**)&pprojw,g_projw);
    cudaGetSymbolAddress((void**)&pfc1w, g_fc1w);
    cudaGetSymbolAddress((void**)&pfc2w, g_fc2w);
    cudaGetSymbolAddress((void**)&pfinw, g_finw);

    const int TOTW = 8*256*1536 + 8*256*512 + 8*256*2048 + 8*1024*512 + 256*1024;
    pack_all_kernel<<<(TOTW/4 + 255)/256, 256>>>(qkv_w, proj_w, fc1_w, fc2_w, fin_w,
                                                 pqkvw, pprojw, pfc1w, pfc2w, pfinw);
    // pos-embed + LN1(layer 0) fused
    add_pe_ln_kernel<<<512, 256>>>(x_in, n1_g, n1_b, px, plnh);

    for (int l = 0; l < 8; l++) {
        const uint32_t* qw  = pqkvw  + (size_t)l * 256 * 1536;
        const uint32_t* pw  = pprojw + (size_t)l * 256 * 512;
        const uint32_t* f1w = pfc1w  + (size_t)l * 256 * 2048;
        const uint32_t* f2w = pfc2w  + (size_t)l * 1024 * 512;
        const float* qb  = qkv_b  + (size_t)l * 1536;
        const float* pb  = proj_b + (size_t)l * 512;
        const float* f1b = fc1_b  + (size_t)l * 2048;
        const float* f2b = fc2_b  + (size_t)l * 512;

        sgemm_qkv_kernel<<<dim3(12, 32), 256>>>(plnh, qw, qb,
                                                nq_g + l * 32, nq_b + l * 32,
                                                nk_g + l * 32, nk_b + l * 32,
                                                pq, pk, pv);
        flash_kernel<<<dim3(8, 64), 256>>>(pq, pk, pv, poh);
        sgemm_h16_n64_kernel<<<dim3(8, 32), 256>>>(poh, pw, pb, px, px2,
                                                   4096, 512, 512);
        ln_kernel<<<512, 256>>>(px2, n2_g + l * 512, n2_b + l * 512, plnh, 1e-5f);
        sgemm_h16_kernel<<<dim3(16, 32), 256>>>(plnh, f1w, f1b, nullptr, nullptr, pmlph,
                                                4096, 2048, 512, 2);
        sgemm_h16_n64_kernel<<<dim3(8, 32), 256>>>(pmlph, f2w, f2b, px2, px,
                                                   4096, 512, 2048);
        // LN1 for next layer (or final LN after last layer)
        if (l < 7)
            ln_kernel<<<512, 256>>>(px, n1_g + (l + 1) * 512, n1_b + (l + 1) * 512,
                                    plnh, 1e-5f);
        else
            ln_kernel<<<512, 256>>>(px, nullptr, nullptr, plnh, 1e-6f);
    }

    sgemm_h16_kernel<<<dim3(8, 32), 256>>>(plnh, pfinw, fin_b, nullptr, pfin, nullptr,
                                           4096, 1024, 512, 0);
    unpatch_kernel<<<(4 * 64 * 128 * 128 + 255) / 256, 256>>>(pfin, pimg);
    conv1_kernel<<<dim3(64, 4), 256>>>(pimg, c1_w, c1_b, pc1);
    conv2_kernel<<<(4 * 3 * 128 * 128 + 255) / 256, 256>>>(pc1, c2_w, c2_b, out);
}

// round 17
// speedup vs baseline: 1.0558x; 1.0036x over previous
#include <cuda_runtime.h>
#include <cuda_fp16.h>
#include <math.h>
#include <stdint.h>

// ---------------- scratch (static device globals; no allocations) ----------
__device__ float    g_x   [4096*512];
__device__ float    g_x2  [4096*512];
__device__ uint32_t g_lnh [4096*256];     // LN output, half2 words
__device__ uint32_t g_mlph[4096*1024];    // fc1 output, half2 words
__device__ uint32_t g_q   [64*1024*16];   // half2 words, [bh][n][16]
__device__ uint32_t g_k   [64*1024*16];
__device__ uint32_t g_v   [64*1024*16];
__device__ uint32_t g_oh  [4096*256];     // flash output, half2 words
__device__ float    g_fin [4096*1024];
__device__ float    g_img [4*64*128*128];
__device__ float    g_c1  [4*16*128*128];
// packed weights (k-paired half2 words, [K/2][N])
__device__ uint32_t g_qkvw[8*256*1536];
__device__ uint32_t g_projw[8*256*512];
__device__ uint32_t g_fc1w[8*256*2048];
__device__ uint32_t g_fc2w[8*1024*512];
__device__ uint32_t g_finw[256*1024];

// ---------------- helpers --------------------------------------------------
__device__ __forceinline__ uint32_t h2u(__half2 h) {
    return *reinterpret_cast<uint32_t*>(&h);
}

__device__ __forceinline__ float ex2(float x) {
    float y;
    asm("ex2.approx.ftz.f32 %0, %1;" : "=f"(y) : "f"(x));
    return y;
}

__device__ __forceinline__ void mma_f16(float* c, const uint32_t* a, const uint32_t* b) {
    asm volatile(
        "mma.sync.aligned.m16n8k16.row.col.f32.f16.f16.f32 "
        "{%0,%1,%2,%3}, {%4,%5,%6,%7}, {%8,%9}, {%0,%1,%2,%3};"
        : "+f"(c[0]), "+f"(c[1]), "+f"(c[2]), "+f"(c[3])
        : "r"(a[0]), "r"(a[1]), "r"(a[2]), "r"(a[3]), "r"(b[0]), "r"(b[1]));
}

__device__ __forceinline__ void ldsm_x4(uint32_t& r0, uint32_t& r1, uint32_t& r2,
                                        uint32_t& r3, uint32_t addr) {
    asm volatile("ldmatrix.sync.aligned.m8n8.x4.shared.b16 {%0,%1,%2,%3}, [%4];"
        : "=r"(r0), "=r"(r1), "=r"(r2), "=r"(r3) : "r"(addr));
}

// ---------------- merged weight pack ---------------------------------------
__global__ void pack_all_kernel(const float* __restrict__ qkv_w, const float* __restrict__ proj_w,
                                const float* __restrict__ fc1_w, const float* __restrict__ fc2_w,
                                const float* __restrict__ fin_w,
                                uint32_t* __restrict__ qkvp, uint32_t* __restrict__ projp,
                                uint32_t* __restrict__ fc1p, uint32_t* __restrict__ fc2p,
                                uint32_t* __restrict__ finp) {
    const int S0 = 8*256*1536, S1 = S0 + 8*256*512, S2 = S1 + 8*256*2048,
              S3 = S2 + 8*1024*512, S4 = S3 + 256*1024;
    int t = (blockIdx.x * blockDim.x + threadIdx.x) * 4;
    if (t >= S4) return;
    const float* src; uint32_t* dst; int N; int base;
    if (t < S0)      { src = qkv_w;  dst = qkvp;  N = 1536; base = t; }
    else if (t < S1) { src = proj_w; dst = projp; N = 512;  base = t - S0; }
    else if (t < S2) { src = fc1_w;  dst = fc1p;  N = 2048; base = t - S1; }
    else if (t < S3) { src = fc2_w;  dst = fc2p;  N = 512;  base = t - S2; }
    else             { src = fin_w;  dst = finp;  N = 1024; base = t - S3; }
    int p = base / N, n = base - p * N;
    float4 r0 = *(const float4*)&src[(size_t)(2 * p) * N + n];
    float4 r1 = *(const float4*)&src[(size_t)(2 * p + 1) * N + n];
    uint4 o;
    o.x = h2u(__floats2half2_rn(r0.x, r1.x));
    o.y = h2u(__floats2half2_rn(r0.y, r1.y));
    o.z = h2u(__floats2half2_rn(r0.z, r1.z));
    o.w = h2u(__floats2half2_rn(r0.w, r1.w));
    *(uint4*)&dst[base] = o;
}

// ---------------- pos-embed add + LN (layer 0), warp per row ---------------
__global__ void add_pe_ln_kernel(const float* __restrict__ x,
                                 const float* __restrict__ gam, const float* __restrict__ bet,
                                 float* __restrict__ outF, uint32_t* __restrict__ outH) {
    int row = (blockIdx.x * blockDim.x + threadIdx.x) >> 5;
    int lane = threadIdx.x & 31;
    if (row >= 4096) return;
    int p = row & 1023;
    int pi = p >> 5, pj = p & 31;
    const float4* xp = (const float4*)(x + (size_t)row * 512);
    float4 v[4];
    float s = 0.f;
#pragma unroll
    for (int i = 0; i < 4; i++) {
        v[i] = xp[lane + i * 32];
        int c0 = (lane + i * 32) * 4;
        float* vf = (float*)&v[i];
#pragma unroll
        for (int j = 0; j < 4; j++) {
            int c = c0 + j;
            int pos = (c < 256) ? pj : pi;
            int cc = c & 255;
            int m = cc & 127;
            float om = __expf(-(float)m * 0.0719558141f);
            float a = (float)pos * om;
            vf[j] += (cc < 128) ? sinf(a) : cosf(a);
        }
        s += v[i].x + v[i].y + v[i].z + v[i].w;
    }
#pragma unroll
    for (int o = 16; o > 0; o >>= 1) s += __shfl_xor_sync(0xffffffffu, s, o);
    float mu = s * (1.f / 512.f);
    float sq = 0.f;
#pragma unroll
    for (int i = 0; i < 4; i++) {
        float dx = v[i].x - mu, dy = v[i].y - mu, dz = v[i].z - mu, dw = v[i].w - mu;
        sq += dx * dx + dy * dy + dz * dz + dw * dw;
    }
#pragma unroll
    for (int o = 16; o > 0; o >>= 1) sq += __shfl_xor_sync(0xffffffffu, sq, o);
    float rstd = rsqrtf(sq * (1.f / 512.f) + 1e-5f);
    float4* fp = (float4*)(outF + (size_t)row * 512);
    uint32_t* op = outH + (size_t)row * 256;
#pragma unroll
    for (int i = 0; i < 4; i++) {
        fp[lane + i * 32] = v[i];
        float4 gg = ((const float4*)gam)[lane + i * 32];
        float4 bb = ((const float4*)bet)[lane + i * 32];
        float y0 = (v[i].x - mu) * rstd * gg.x + bb.x;
        float y1 = (v[i].y - mu) * rstd * gg.y + bb.y;
        float y2 = (v[i].z - mu) * rstd * gg.z + bb.z;
        float y3 = (v[i].w - mu) * rstd * gg.w + bb.w;
        uint2 wds;
        wds.x = h2u(__floats2half2_rn(y0, y1));
        wds.y = h2u(__floats2half2_rn(y2, y3));
        *(uint2*)&op[2 * (lane + i * 32)] = wds;
    }
}

// ---------------- layernorm: warp/row, fp32 in -> half2 out ---------------
__global__ void ln_kernel(const float* __restrict__ in, const float* __restrict__ g,
                          const float* __restrict__ b, uint32_t* __restrict__ out,
                          float eps) {
    int row = (blockIdx.x * blockDim.x + threadIdx.x) >> 5;
    int lane = threadIdx.x & 31;
    if (row >= 4096) return;
    const float4* x = (const float4*)(in + (size_t)row * 512);
    float4 v[4];
    float s = 0.f;
#pragma unroll
    for (int i = 0; i < 4; i++) {
        v[i] = x[lane + i * 32];
        s += v[i].x + v[i].y + v[i].z + v[i].w;
    }
#pragma unroll
    for (int o = 16; o > 0; o >>= 1) s += __shfl_xor_sync(0xffffffffu, s, o);
    float mu = s * (1.f / 512.f);
    float sq = 0.f;
#pragma unroll
    for (int i = 0; i < 4; i++) {
        float dx = v[i].x - mu, dy = v[i].y - mu, dz = v[i].z - mu, dw = v[i].w - mu;
        sq += dx * dx + dy * dy + dz * dz + dw * dw;
    }
#pragma unroll
    for (int o = 16; o > 0; o >>= 1) sq += __shfl_xor_sync(0xffffffffu, sq, o);
    float rstd = rsqrtf(sq * (1.f / 512.f) + eps);
    uint32_t* op = out + (size_t)row * 256;
#pragma unroll
    for (int i = 0; i < 4; i++) {
        float4 y;
        y.x = (v[i].x - mu) * rstd; y.y = (v[i].y - mu) * rstd;
        y.z = (v[i].z - mu) * rstd; y.w = (v[i].w - mu) * rstd;
        if (g) {
            float4 gg = ((const float4*)g)[lane + i * 32];
            float4 bb = ((const float4*)b)[lane + i * 32];
            y.x = y.x * gg.x + bb.x; y.y = y.y * gg.y + bb.y;
            y.z = y.z * gg.z + bb.z; y.w = y.w * gg.w + bb.w;
        }
        uint2 wds;
        wds.x = h2u(__floats2half2_rn(y.x, y.y));
        wds.y = h2u(__floats2half2_rn(y.z, y.w));
        *(uint2*)&op[2 * (lane + i * 32)] = wds;
    }
}

// ---------------- fp16-operand GEMM, 128x128 tile (ldmatrix A) -------------
// mode 0: Cf=acc+bias; 1: Cf=acc+bias+res; 2: Ch=half(GELU(acc+bias)).
__global__ void __launch_bounds__(256) sgemm_h16_kernel(
        const uint32_t* __restrict__ A, const uint32_t* __restrict__ B,
        const float* __restrict__ bias, const float* __restrict__ res,
        float* __restrict__ Cf, uint32_t* __restrict__ Ch,
        int M, int N, int K, int mode) {
    __shared__ uint32_t As[128 * 20];
    __shared__ uint32_t Bs[16 * 136];
    int tid = threadIdx.x;
    int w = tid >> 5, lane = tid & 31;
    int g = lane >> 2, tig = lane & 3;
    int warp_m = w & 1, warp_n = w >> 1;
    int bm = blockIdx.y * 128, bn = blockIdx.x * 128;
    int Kw = K >> 1;

    int arow[2], ac4[2], bp[2], bn4[2];
#pragma unroll
    for (int i = 0; i < 2; i++) {
        int idx = i * 256 + tid;
        arow[i] = idx >> 2;  ac4[i] = idx & 3;
        bp[i]   = idx >> 5;  bn4[i] = idx & 31;
    }
    uint32_t as_base = (uint32_t)__cvta_generic_to_shared(As);
    uint32_t a_addr = as_base + (((warp_m * 64 + (lane & 15)) * 20 + (lane >> 4) * 4) << 2);

    float acc[4][4][4] = {};
    uint4 pa[2], pb[2];
#pragma unroll
    for (int i = 0; i < 2; i++) {
        pa[i] = *(const uint4*)&A[(size_t)(bm + arow[i]) * Kw + ac4[i] * 4];
        pb[i] = *(const uint4*)&B[(size_t)bp[i] * N + bn + bn4[i] * 4];
    }

    for (int k0 = 0; k0 < K; k0 += 32) {
#pragma unroll
        for (int i = 0; i < 2; i++) {
            *(uint4*)&As[arow[i] * 20 + ac4[i] * 4] = pa[i];
            *(uint4*)&Bs[bp[i] * 136 + bn4[i] * 4] = pb[i];
        }
        __syncthreads();
        if (k0 + 32 < K) {
            int kw0 = (k0 + 32) >> 1;
#pragma unroll
            for (int i = 0; i < 2; i++) {
                pa[i] = *(const uint4*)&A[(size_t)(bm + arow[i]) * Kw + kw0 + ac4[i] * 4];
                pb[i] = *(const uint4*)&B[(size_t)(kw0 + bp[i]) * N + bn + bn4[i] * 4];
            }
        }
#pragma unroll
        for (int ks = 0; ks < 2; ks++) {
            int kw = ks * 8;
            uint32_t a[4][4], b[4][2];
#pragma unroll
            for (int mt = 0; mt < 4; mt++)
                ldsm_x4(a[mt][0], a[mt][1], a[mt][2], a[mt][3],
                        a_addr + mt * 1280 + ks * 32);
#pragma unroll
            for (int nt = 0; nt < 4; nt++) {
                int nc = warp_n * 32 + nt * 8;
                b[nt][0] = Bs[(kw + tig) * 136 + nc + g];
                b[nt][1] = Bs[(kw + 4 + tig) * 136 + nc + g];
            }
#pragma unroll
            for (int mt = 0; mt < 4; mt++)
#pragma unroll
                for (int nt = 0; nt < 4; nt++)
                    mma_f16(acc[mt][nt], a[mt], b[nt]);
        }
        __syncthreads();
    }

#pragma unroll
    for (int mt = 0; mt < 4; mt++) {
#pragma unroll
        for (int nt = 0; nt < 4; nt++) {
            int row0 = bm + warp_m * 64 + mt * 16 + g;
            int col0 = bn + warp_n * 32 + nt * 8 + 2 * tig;
            if (mode == 2) {
#pragma unroll
                for (int rh = 0; rh < 2; rh++) {
                    int row = row0 + rh * 8;
                    float v0 = acc[mt][nt][rh * 2]     + bias[col0];
                    float v1 = acc[mt][nt][rh * 2 + 1] + bias[col0 + 1];
                    v0 = 0.5f * v0 * (1.f + erff(v0 * 0.70710678118654752f));
                    v1 = 0.5f * v1 * (1.f + erff(v1 * 0.70710678118654752f));
                    Ch[(size_t)row * (N >> 1) + (col0 >> 1)] = h2u(__floats2half2_rn(v0, v1));
                }
            } else {
#pragma unroll
                for (int i = 0; i < 4; i++) {
                    int row = row0 + (i >> 1) * 8;
                    int col = col0 + (i & 1);
                    float v = acc[mt][nt][i] + bias[col];
                    if (mode == 1) v += res[(size_t)row * N + col];
                    Cf[(size_t)row * N + col] = v;
                }
            }
        }
    }
}

// ---------------- fp16-operand GEMM, 128x64 tile (for N=512 GEMMs) --------
__global__ void __launch_bounds__(256) sgemm_h16_n64_kernel(
        const uint32_t* __restrict__ A, const uint32_t* __restrict__ B,
        const float* __restrict__ bias, const float* __restrict__ res,
        float* __restrict__ Cf, int M, int N, int K) {
    __shared__ uint32_t As[128 * 20];
    __shared__ uint32_t Bs[16 * 72];
    int tid = threadIdx.x;
    int w = tid >> 5, lane = tid & 31;
    int g = lane >> 2, tig = lane & 3;
    int warp_m = w & 3, warp_n = w >> 2;
    int bm = blockIdx.y * 128, bn = blockIdx.x * 64;
    int Kw = K >> 1;

    int arow[2], ac4[2];
#pragma unroll
    for (int i = 0; i < 2; i++) {
        int idx = i * 256 + tid;
        arow[i] = idx >> 2;  ac4[i] = idx & 3;
    }
    int bp = tid >> 4, bn4 = tid & 15;
    uint32_t as_base = (uint32_t)__cvta_generic_to_shared(As);
    uint32_t a_addr = as_base + (((warp_m * 32 + (lane & 15)) * 20 + (lane >> 4) * 4) << 2);

    float acc[2][4][4] = {};
    uint4 pa[2], pb;
#pragma unroll
    for (int i = 0; i < 2; i++)
        pa[i] = *(const uint4*)&A[(size_t)(bm + arow[i]) * Kw + ac4[i] * 4];
    pb = *(const uint4*)&B[(size_t)bp * N + bn + bn4 * 4];

    for (int k0 = 0; k0 < K; k0 += 32) {
#pragma unroll
        for (int i = 0; i < 2; i++)
            *(uint4*)&As[arow[i] * 20 + ac4[i] * 4] = pa[i];
        *(uint4*)&Bs[bp * 72 + bn4 * 4] = pb;
        __syncthreads();
        if (k0 + 32 < K) {
            int kw0 = (k0 + 32) >> 1;
#pragma unroll
            for (int i = 0; i < 2; i++)
                pa[i] = *(const uint4*)&A[(size_t)(bm + arow[i]) * Kw + kw0 + ac4[i] * 4];
            pb = *(const uint4*)&B[(size_t)(kw0 + bp) * N + bn + bn4 * 4];
        }
#pragma unroll
        for (int ks = 0; ks < 2; ks++) {
            int kw = ks * 8;
            uint32_t a[2][4], b[4][2];
#pragma unroll
            for (int mt = 0; mt < 2; mt++)
                ldsm_x4(a[mt][0], a[mt][1], a[mt][2], a[mt][3],
                        a_addr + mt * 1280 + ks * 32);
#pragma unroll
            for (int nt = 0; nt < 4; nt++) {
                int nc = warp_n * 32 + nt * 8;
                b[nt][0] = Bs[(kw + tig) * 72 + nc + g];
                b[nt][1] = Bs[(kw + 4 + tig) * 72 + nc + g];
            }
#pragma unroll
            for (int mt = 0; mt < 2; mt++)
#pragma unroll
                for (int nt = 0; nt < 4; nt++)
                    mma_f16(acc[mt][nt], a[mt], b[nt]);
        }
        __syncthreads();
    }

#pragma unroll
    for (int mt = 0; mt < 2; mt++) {
#pragma unroll
        for (int nt = 0; nt < 4; nt++) {
            int row0 = bm + warp_m * 32 + mt * 16 + g;
            int col0 = bn + warp_n * 32 + nt * 8 + 2 * tig;
#pragma unroll
            for (int i = 0; i < 4; i++) {
                int row = row0 + (i >> 1) * 8;
                int col = col0 + (i & 1);
                Cf[(size_t)row * N + col] = acc[mt][nt][i] + bias[col] + res[(size_t)row * N + col];
            }
        }
    }
}

// ---------------- QKV GEMM (fp16 operands, ldmatrix) + split + head-LN ----
__global__ void __launch_bounds__(256) sgemm_qkv_kernel(
        const uint32_t* __restrict__ A, const uint32_t* __restrict__ B,
        const float* __restrict__ bias,
        const float* __restrict__ nqg, const float* __restrict__ nqb,
        const float* __restrict__ nkg, const float* __restrict__ nkb,
        uint32_t* __restrict__ q, uint32_t* __restrict__ k,
        uint32_t* __restrict__ v) {
    const int N = 1536, K = 512, Kw = 256;
    __shared__ uint32_t As[128 * 20];
    __shared__ uint32_t Bs[16 * 136];
    int tid = threadIdx.x;
    int w = tid >> 5, lane = tid & 31;
    int g = lane >> 2, tig = lane & 3;
    int warp_m = w & 1, warp_n = w >> 1;
    int bm = blockIdx.y * 128, bn = blockIdx.x * 128;

    int arow[2], ac4[2], bp[2], bn4[2];
#pragma unroll
    for (int i = 0; i < 2; i++) {
        int idx = i * 256 + tid;
        arow[i] = idx >> 2;  ac4[i] = idx & 3;
        bp[i]   = idx >> 5;  bn4[i] = idx & 31;
    }
    uint32_t as_base = (uint32_t)__cvta_generic_to_shared(As);
    uint32_t a_addr = as_base + (((warp_m * 64 + (lane & 15)) * 20 + (lane >> 4) * 4) << 2);

    float acc[4][4][4] = {};
    uint4 pa[2], pb[2];
#pragma unroll
    for (int i = 0; i < 2; i++) {
        pa[i] = *(const uint4*)&A[(size_t)(bm + arow[i]) * Kw + ac4[i] * 4];
        pb[i] = *(const uint4*)&B[(size_t)bp[i] * N + bn + bn4[i] * 4];
    }

    for (int k0 = 0; k0 < K; k0 += 32) {
#pragma unroll
        for (int i = 0; i < 2; i++) {
            *(uint4*)&As[arow[i] * 20 + ac4[i] * 4] = pa[i];
            *(uint4*)&Bs[bp[i] * 136 + bn4[i] * 4] = pb[i];
        }
        __syncthreads();
        if (k0 + 32 < K) {
            int kw0 = (k0 + 32) >> 1;
#pragma unroll
            for (int i = 0; i < 2; i++) {
                pa[i] = *(const uint4*)&A[(size_t)(bm + arow[i]) * Kw + kw0 + ac4[i] * 4];
                pb[i] = *(const uint4*)&B[(size_t)(kw0 + bp[i]) * N + bn + bn4[i] * 4];
            }
        }
#pragma unroll
        for (int ks = 0; ks < 2; ks++) {
            int kw = ks * 8;
            uint32_t a[4][4], b[4][2];
#pragma unroll
            for (int mt = 0; mt < 4; mt++)
                ldsm_x4(a[mt][0], a[mt][1], a[mt][2], a[mt][3],
                        a_addr + mt * 1280 + ks * 32);
#pragma unroll
            for (int nt = 0; nt < 4; nt++) {
                int nc = warp_n * 32 + nt * 8;
                b[nt][0] = Bs[(kw + tig) * 136 + nc + g];
                b[nt][1] = Bs[(kw + 4 + tig) * 136 + nc + g];
            }
#pragma unroll
            for (int mt = 0; mt < 4; mt++)
#pragma unroll
                for (int nt = 0; nt < 4; nt++)
                    mma_f16(acc[mt][nt], a[mt], b[nt]);
        }
        __syncthreads();
    }

    int colbase = bn + warp_n * 32;
    int sec = colbase >> 9;
    int h = (colbase & 511) >> 5;
    const float sc = 0.17677669529663689f * 1.4426950408889634f;
    const float* gam = (sec == 0) ? nqg : nkg;
    const float* bet = (sec == 0) ? nqb : nkb;
    uint32_t* dst = (sec == 0) ? q : ((sec == 1) ? k : v);

#pragma unroll
    for (int mt = 0; mt < 4; mt++) {
#pragma unroll
        for (int rh = 0; rh < 2; rh++) {
            int row = bm + warp_m * 64 + mt * 16 + g + rh * 8;
            int bb = row >> 10, n = row & 1023;
            size_t offw = ((size_t)(bb * 16 + h) * 1024 + n) * 16;
            float vv[8];
#pragma unroll
            for (int nt = 0; nt < 4; nt++) {
#pragma unroll
                for (int j = 0; j < 2; j++) {
                    int col = colbase + nt * 8 + 2 * tig + j;
                    vv[nt * 2 + j] = acc[mt][nt][rh * 2 + j] + bias[col];
                }
            }
            if (sec == 2) {
#pragma unroll
                for (int nt = 0; nt < 4; nt++)
                    dst[offw + nt * 4 + tig] = h2u(__floats2half2_rn(vv[nt * 2], vv[nt * 2 + 1]));
            } else {
                float s = 0.f;
#pragma unroll
                for (int t = 0; t < 8; t++) s += vv[t];
                s += __shfl_xor_sync(0xffffffffu, s, 1);
                s += __shfl_xor_sync(0xffffffffu, s, 2);
                float mu = s * (1.f / 32.f);
                float sq = 0.f;
#pragma unroll
                for (int t = 0; t < 8; t++) { float d = vv[t] - mu; sq += d * d; }
                sq += __shfl_xor_sync(0xffffffffu, sq, 1);
                sq += __shfl_xor_sync(0xffffffffu, sq, 2);
                float rstd = rsqrtf(sq * (1.f / 32.f) + 1e-5f);
#pragma unroll
                for (int nt = 0; nt < 4; nt++) {
                    int d = nt * 8 + 2 * tig;
                    float y0 = (vv[nt * 2] - mu) * rstd * gam[d] + bet[d];
                    float y1 = (vv[nt * 2 + 1] - mu) * rstd * gam[d + 1] + bet[d + 1];
                    if (sec == 0) { y0 *= sc; y1 *= sc; }
                    dst[offw + nt * 4 + tig] = h2u(__floats2half2_rn(y0, y1));
                }
            }
        }
    }
}

// ---------------- flash attention: 128-key tiles, ldmatrix, ex2.approx ----
// grid (8 qblocks, 64 bh), 256 thr. Warp owns 16 q rows. 8 iterations.
__global__ void __launch_bounds__(256) flash_kernel(
        const uint32_t* __restrict__ q, const uint32_t* __restrict__ k,
        const uint32_t* __restrict__ v, uint32_t* __restrict__ o) {
    __shared__ uint32_t Qs[128 * 20];
    __shared__ uint32_t Ks[2][128 * 20];
    __shared__ uint32_t Vs[2][32 * 68];

    int bh = blockIdx.y;
    int bm = blockIdx.x * 128;
    int b = bh >> 4, h = bh & 15;
    int tid = threadIdx.x;
    int w = tid >> 5, lane = tid & 31;
    int g = lane >> 2, tig = lane & 3;

    const uint32_t* qb = q + ((size_t)bh * 1024 + bm) * 16;
    const uint32_t* kb = k + (size_t)bh * 1024 * 16;
    const uint32_t* vb = v + (size_t)bh * 1024 * 16;

    // Q fill
#pragma unroll
    for (int i = 0; i < 2; i++) {
        int idx = i * 256 + tid;
        int r = idx >> 2, wv = idx & 3;
        *(uint4*)&Qs[r * 20 + wv * 4] = *(const uint4*)&qb[r * 16 + wv * 4];
    }
    // tile 0 K/V fill (128 keys)
    {
#pragma unroll
        for (int i = 0; i < 2; i++) {
            int idx = i * 256 + tid;
            int r = idx >> 2, wv = idx & 3;
            *(uint4*)&Ks[0][r * 20 + wv * 4] = *(const uint4*)&kb[r * 16 + wv * 4];
        }
#pragma unroll
        for (int i = 0; i < 4; i++) {
            int idx = i * 256 + tid;
            int p = idx >> 4, dp = idx & 15;
            uint32_t a = vb[(size_t)(2 * p) * 16 + dp];
            uint32_t bw = vb[(size_t)(2 * p + 1) * 16 + dp];
            Vs[0][(2 * dp) * 68 + p]     = __byte_perm(a, bw, 0x5410);
            Vs[0][(2 * dp + 1) * 68 + p] = __byte_perm(a, bw, 0x7632);
        }
    }
    __syncthreads();

    int frow = (lane & 7) + ((lane & 16) >> 1);
    int fcol = (lane & 8) >> 1;
    uint32_t qs_base = (uint32_t)__cvta_generic_to_shared(Qs);
    uint32_t ks_base0 = (uint32_t)__cvta_generic_to_shared(&Ks[0][0]);
    uint32_t vs_base0 = (uint32_t)__cvta_generic_to_shared(&Vs[0][0]);

    uint32_t qa[2][4];
    {
        uint32_t qaddr = qs_base + (((w * 16 + (lane & 15)) * 20 + (lane >> 4) * 4) << 2);
        ldsm_x4(qa[0][0], qa[0][1], qa[0][2], qa[0][3], qaddr);
        ldsm_x4(qa[1][0], qa[1][1], qa[1][2], qa[1][3], qaddr + 32);
    }

    float oacc[4][4] = {};
    float m0 = -1e30f, m1 = -1e30f, l0 = 0.f, l1 = 0.f;

    for (int j = 0; j < 8; j++) {
        int cur = j & 1;
        uint32_t ks_b = ks_base0 + cur * (128 * 20 * 4);
        uint32_t vs_b = vs_base0 + cur * (32 * 68 * 4);
        uint4 kreg[2];
        uint32_t va[4], vbw[4];
        if (j < 7) {
#pragma unroll
            for (int i = 0; i < 2; i++) {
                int idx = i * 256 + tid;
                int r = idx >> 2, wv = idx & 3;
                kreg[i] = *(const uint4*)&kb[(size_t)((j + 1) * 128 + r) * 16 + wv * 4];
            }
#pragma unroll
            for (int i = 0; i < 4; i++) {
                int idx = i * 256 + tid;
                int p = idx >> 4, dp = idx & 15;
                va[i]  = vb[(size_t)((j + 1) * 128 + 2 * p) * 16 + dp];
                vbw[i] = vb[(size_t)((j + 1) * 128 + 2 * p + 1) * 16 + dp];
            }
        }

        // S = Q K^T : warp computes 16x128
        float s[16][4] = {};
#pragma unroll
        for (int ks = 0; ks < 2; ks++) {
            uint32_t bf[16][2];
#pragma unroll
            for (int tp = 0; tp < 8; tp++) {
                uint32_t addr = ks_b + (((tp * 16 + frow) * 20 + ks * 8 + fcol) << 2);
                ldsm_x4(bf[2 * tp][0], bf[2 * tp][1], bf[2 * tp + 1][0], bf[2 * tp + 1][1], addr);
            }
#pragma unroll
            for (int nt = 0; nt < 16; nt++)
                mma_f16(s[nt], qa[ks], bf[nt]);
        }

        // online softmax in log2 domain (rows g and g+8)
        float rm0 = -1e30f, rm1 = -1e30f;
#pragma unroll
        for (int nt = 0; nt < 16; nt++) {
            rm0 = fmaxf(rm0, fmaxf(s[nt][0], s[nt][1]));
            rm1 = fmaxf(rm1, fmaxf(s[nt][2], s[nt][3]));
        }
        rm0 = fmaxf(rm0, __shfl_xor_sync(0xffffffffu, rm0, 1));
        rm0 = fmaxf(rm0, __shfl_xor_sync(0xffffffffu, rm0, 2));
        rm1 = fmaxf(rm1, __shfl_xor_sync(0xffffffffu, rm1, 1));
        rm1 = fmaxf(rm1, __shfl_xor_sync(0xffffffffu, rm1, 2));
        float nm0 = fmaxf(m0, rm0), nm1 = fmaxf(m1, rm1);
        float al0 = ex2(m0 - nm0), al1 = ex2(m1 - nm1);
        float rs0 = 0.f, rs1 = 0.f;
#pragma unroll
        for (int nt = 0; nt < 16; nt++) {
            s[nt][0] = ex2(s[nt][0] - nm0);
            s[nt][1] = ex2(s[nt][1] - nm0);
            s[nt][2] = ex2(s[nt][2] - nm1);
            s[nt][3] = ex2(s[nt][3] - nm1);
            rs0 += s[nt][0] + s[nt][1];
            rs1 += s[nt][2] + s[nt][3];
        }
        rs0 += __shfl_xor_sync(0xffffffffu, rs0, 1);
        rs0 += __shfl_xor_sync(0xffffffffu, rs0, 2);
        rs1 += __shfl_xor_sync(0xffffffffu, rs1, 1);
        rs1 += __shfl_xor_sync(0xffffffffu, rs1, 2);
        l0 = l0 * al0 + rs0;
        l1 = l1 * al1 + rs1;
        m0 = nm0; m1 = nm1;
#pragma unroll
        for (int nt = 0; nt < 4; nt++) {
            oacc[nt][0] *= al0; oacc[nt][1] *= al0;
            oacc[nt][2] *= al1; oacc[nt][3] *= al1;
        }

        // O += P @ V : 8 ks2 steps of 16 keys
#pragma unroll
        for (int ks2 = 0; ks2 < 8; ks2++) {
            uint32_t a[4];
            a[0] = h2u(__floats2half2_rn(s[2 * ks2][0],     s[2 * ks2][1]));
            a[1] = h2u(__floats2half2_rn(s[2 * ks2][2],     s[2 * ks2][3]));
            a[2] = h2u(__floats2half2_rn(s[2 * ks2 + 1][0], s[2 * ks2 + 1][1]));
            a[3] = h2u(__floats2half2_rn(s[2 * ks2 + 1][2], s[2 * ks2 + 1][3]));
            uint32_t bf[4][2];
#pragma unroll
            for (int tp = 0; tp < 2; tp++) {
                uint32_t addr = vs_b + (((tp * 16 + frow) * 68 + ks2 * 8 + fcol) << 2);
                ldsm_x4(bf[2 * tp][0], bf[2 * tp][1], bf[2 * tp + 1][0], bf[2 * tp + 1][1], addr);
            }
#pragma unroll
            for (int nt = 0; nt < 4; nt++)
                mma_f16(oacc[nt], a, bf[nt]);
        }

        if (j < 7) {
            int nxt = cur ^ 1;
#pragma unroll
            for (int i = 0; i < 2; i++) {
                int idx = i * 256 + tid;
                int r = idx >> 2, wv = idx & 3;
                *(uint4*)&Ks[nxt][r * 20 + wv * 4] = kreg[i];
            }
#pragma unroll
            for (int i = 0; i < 4; i++) {
                int idx = i * 256 + tid;
                int p = idx >> 4, dp = idx & 15;
                Vs[nxt][(2 * dp) * 68 + p]     = __byte_perm(va[i], vbw[i], 0x5410);
                Vs[nxt][(2 * dp + 1) * 68 + p] = __byte_perm(va[i], vbw[i], 0x7632);
            }
        }
        __syncthreads();
    }

    float il0 = 1.f / l0, il1 = 1.f / l1;
    int n0 = bm + w * 16 + g;
    size_t ob0 = (size_t)(b * 1024 + n0) * 256;
    size_t ob1 = (size_t)(b * 1024 + n0 + 8) * 256;
#pragma unroll
    for (int nt = 0; nt < 4; nt++) {
        int wd = h * 16 + nt * 4 + tig;
        o[ob0 + wd] = h2u(__floats2half2_rn(oacc[nt][0] * il0, oacc[nt][1] * il0));
        o[ob1 + wd] = h2u(__floats2half2_rn(oacc[nt][2] * il1, oacc[nt][3] * il1));
    }
}

// ---------------- unpatchify ----------------------------------------------
__global__ void unpatch_kernel(const float* __restrict__ fin, float* __restrict__ img) {
    int idx = blockIdx.x * blockDim.x + threadIdx.x;
    if (idx >= 4 * 64 * 128 * 128) return;
    int W = idx & 127;
    int H = (idx >> 7) & 127;
    int c = (idx >> 14) & 63;
    int b = idx >> 20;
    int hh = H >> 2, p = H & 3, ww = W >> 2, qq = W & 3;
    img[idx] = fin[((size_t)(b * 1024 + hh * 32 + ww)) * 1024 + c * 16 + p * 4 + qq];
}

// ---------------- conv1: smem-tiled 3x3, 64->16 ch, ReLU -------------------
__global__ void conv1_kernel(const float* __restrict__ img, const float* __restrict__ w,
                             const float* __restrict__ bias, float* __restrict__ out) {
    __shared__ float patch[18 * 18];
    __shared__ float wsm[16 * 9];
    int b = blockIdx.y;
    int tile = blockIdx.x;
    int Y0 = (tile >> 3) * 16, X0 = (tile & 7) * 16;
    int tid = threadIdx.x;
    int ty = tid >> 4, tx = tid & 15;
    float acc[16];
#pragma unroll
    for (int oc = 0; oc < 16; oc++) acc[oc] = bias[oc];

    for (int ic = 0; ic < 64; ic++) {
        __syncthreads();
        const float* ip = img + ((size_t)(b * 64 + ic)) * 16384;
        for (int idx = tid; idx < 324; idx += 256) {
            int py = idx / 18, px = idx % 18;
            int gy = Y0 + py - 1, gx = X0 + px - 1;
            patch[idx] = (gy >= 0 && gy < 128 && gx >= 0 && gx < 128) ? ip[gy * 128 + gx] : 0.f;
        }
        if (tid < 144) wsm[tid] = w[(size_t)((tid / 9) * 64 + ic) * 9 + (tid % 9)];
        __syncthreads();
        float p[9];
#pragma unroll
        for (int ky = 0; ky < 3; ky++)
#pragma unroll
            for (int kx = 0; kx < 3; kx++)
                p[ky * 3 + kx] = patch[(ty + ky) * 18 + tx + kx];
#pragma unroll
        for (int oc = 0; oc < 16; oc++) {
            float a = 0.f;
#pragma unroll
            for (int t = 0; t < 9; t++) a += p[t] * wsm[oc * 9 + t];
            acc[oc] += a;
        }
    }
#pragma unroll
    for (int oc = 0; oc < 16; oc++)
        out[((size_t)(b * 16 + oc)) * 16384 + (Y0 + ty) * 128 + X0 + tx] = fmaxf(acc[oc], 0.f);
}

// ---------------- conv2: 3x3, 16->3 ch -------------------------------------
__global__ void conv2_kernel(const float* __restrict__ img, const float* __restrict__ w,
                             const float* __restrict__ bias, float* __restrict__ out) {
    int idx = blockIdx.x * blockDim.x + threadIdx.x;
    if (idx >= 4 * 3 * 128 * 128) return;
    int x = idx & 127, y = (idx >> 7) & 127;
    int oc = (idx >> 14) % 3, b = idx / (3 * 16384);
    float acc = bias[oc];
    for (int ic = 0; ic < 16; ic++) {
        const float* ip = img + ((size_t)(b * 16 + ic)) * 16384;
        const float* wp = w + (size_t)(oc * 16 + ic) * 9;
#pragma unroll
        for (int ky = 0; ky < 3; ky++) {
            int yy = y + ky - 1;
            if (yy < 0 || yy > 127) continue;
#pragma unroll
            for (int kx = 0; kx < 3; kx++) {
                int xx = x + kx - 1;
                if (xx < 0 || xx > 127) continue;
                acc += ip[yy * 128 + xx] * wp[ky * 3 + kx];
            }
        }
    }
    out[idx] = acc;
}

// ---------------- driver ---------------------------------------------------
extern "C" void kernel_launch(void* const* d_in, const int* in_sizes, int n_in,
                              void* d_out, int out_size) {
    const float* x_in  = (const float*)d_in[0];
    const float* qkv_w = (const float*)d_in[1];
    const float* qkv_b = (const float*)d_in[2];
    const float* proj_w= (const float*)d_in[3];
    const float* proj_b= (const float*)d_in[4];
    const float* nq_g  = (const float*)d_in[5];
    const float* nq_b  = (const float*)d_in[6];
    const float* nk_g  = (const float*)d_in[7];
    const float* nk_b  = (const float*)d_in[8];
    const float* n1_g  = (const float*)d_in[9];
    const float* n1_b  = (const float*)d_in[10];
    const float* n2_g  = (const float*)d_in[11];
    const float* n2_b  = (const float*)d_in[12];
    const float* fc1_w = (const float*)d_in[13];
    const float* fc1_b = (const float*)d_in[14];
    const float* fc2_w = (const float*)d_in[15];
    const float* fc2_b = (const float*)d_in[16];
    const float* fin_w = (const float*)d_in[17];
    const float* fin_b = (const float*)d_in[18];
    const float* c1_w  = (const float*)d_in[19];
    const float* c1_b  = (const float*)d_in[20];
    const float* c2_w  = (const float*)d_in[21];
    const float* c2_b  = (const float*)d_in[22];
    float* out = (float*)d_out;

    float *px, *px2, *pfin, *pimg, *pc1;
    uint32_t *plnh, *pmlph, *pq, *pk, *pv, *poh;
    uint32_t *pqkvw, *pprojw, *pfc1w, *pfc2w, *pfinw;
    cudaGetSymbolAddress((void**)&px,    g_x);
    cudaGetSymbolAddress((void**)&px2,   g_x2);
    cudaGetSymbolAddress((void**)&plnh,  g_lnh);
    cudaGetSymbolAddress((void**)&pmlph, g_mlph);
    cudaGetSymbolAddress((void**)&pq,    g_q);
    cudaGetSymbolAddress((void**)&pk,    g_k);
    cudaGetSymbolAddress((void**)&pv,    g_v);
    cudaGetSymbolAddress((void**)&poh,   g_oh);
    cudaGetSymbolAddress((void**)&pfin,  g_fin);
    cudaGetSymbolAddress((void**)&pimg,  g_img);
    cudaGetSymbolAddress((void**)&pc1,   g_c1);
    cudaGetSymbolAddress((void**)&pqkvw, g_qkvw);
    cudaGetSymbolAddress((void**)&pprojw,g_projw);
    cudaGetSymbolAddress((void**)&pfc1w, g_fc1w);
    cudaGetSymbolAddress((void**)&pfc2w, g_fc2w);
    cudaGetSymbolAddress((void**)&pfinw, g_finw);

    const int TOTW = 8*256*1536 + 8*256*512 + 8*256*2048 + 8*1024*512 + 256*1024;
    pack_all_kernel<<<(TOTW/4 + 255)/256, 256>>>(qkv_w, proj_w, fc1_w, fc2_w, fin_w,
                                                 pqkvw, pprojw, pfc1w, pfc2w, pfinw);
    add_pe_ln_kernel<<<512, 256>>>(x_in, n1_g, n1_b, px, plnh);

    for (int l = 0; l < 8; l++) {
        const uint32_t* qw  = pqkvw  + (size_t)l * 256 * 1536;
        const uint32_t* pw  = pprojw + (size_t)l * 256 * 512;
        const uint32_t* f1w = pfc1w  + (size_t)l * 256 * 2048;
        const uint32_t* f2w = pfc2w  + (size_t)l * 1024 * 512;
        const float* qb  = qkv_b  + (size_t)l * 1536;
        const float* pb  = proj_b + (size_t)l * 512;
        const float* f1b = fc1_b  + (size_t)l * 2048;
        const float* f2b = fc2_b  + (size_t)l * 512;

        sgemm_qkv_kernel<<<dim3(12, 32), 256>>>(plnh, qw, qb,
                                                nq_g + l * 32, nq_b + l * 32,
                                                nk_g + l * 32, nk_b + l * 32,
                                                pq, pk, pv);
        flash_kernel<<<dim3(8, 64), 256>>>(pq, pk, pv, poh);
        sgemm_h16_n64_kernel<<<dim3(8, 32), 256>>>(poh, pw, pb, px, px2,
                                                   4096, 512, 512);
        ln_kernel<<<512, 256>>>(px2, n2_g + l * 512, n2_b + l * 512, plnh, 1e-5f);
        sgemm_h16_kernel<<<dim3(16, 32), 256>>>(plnh, f1w, f1b, nullptr, nullptr, pmlph,
                                                4096, 2048, 512, 2);
        sgemm_h16_n64_kernel<<<dim3(8, 32), 256>>>(pmlph, f2w, f2b, px2, px,
                                                   4096, 512, 2048);
        if (l < 7)
            ln_kernel<<<512, 256>>>(px, n1_g + (l + 1) * 512, n1_b + (l + 1) * 512,
                                    plnh, 1e-5f);
        else
            ln_kernel<<<512, 256>>>(px, nullptr, nullptr, plnh, 1e-6f);
    }

    sgemm_h16_kernel<<<dim3(8, 32), 256>>>(plnh, pfinw, fin_b, nullptr, pfin, nullptr,
                                           4096, 1024, 512, 0);
    unpatch_kernel<<<(4 * 64 * 128 * 128 + 255) / 256, 256>>>(pfin, pimg);
    conv1_kernel<<<dim3(64, 4), 256>>>(pimg, c1_w, c1_b, pc1);
    conv2_kernel<<<(4 * 3 * 128 * 128 + 255) / 256, 256>>>(pc1, c2_w, c2_b, out);
}